// round 3
// baseline (speedup 1.0000x reference)
#include <cuda_runtime.h>
#include <math.h>

#define NT 2048      // B*T tokens
#define DD 128       // d_model
#define TT 512
#define BB 4
#define HH 8
#define HDIM 16
#define EE 256
#define RR 32
#define EPS 1e-6f

// ---------------- scratch (device globals: allocation-free) ----------------
__device__ float g_h1[NT*DD];
__device__ float g_q [NT*DD];
__device__ float g_k [NT*DD];
__device__ float g_v [NT*DD];
__device__ float g_ctx[BB*HH*HDIM*HDIM];   // [b][h][d][e]
__device__ float g_ksum[BB*HH*HDIM];       // [b][h][d]
__device__ float g_z [NT*HH];              // per (token, head)
__device__ float g_x2[NT*DD];
__device__ float g_h2[NT*DD];
__device__ float g_y [NT*2*DD];            // top-2 expert outputs y1,y2
__device__ float g_wavg[NT*DD];            // pre-swiglu weighted avg
__device__ int   g_eidx[NT*2];
__device__ float g_ew [NT*2];

// ---------------- helpers ----------------
__device__ __forceinline__ float warp_sum(float v){
#pragma unroll
    for (int o = 16; o > 0; o >>= 1) v += __shfl_xor_sync(0xffffffffu, v, o);
    return v;
}
__device__ __forceinline__ float warp_max(float v){
#pragma unroll
    for (int o = 16; o > 0; o >>= 1) v = fmaxf(v, __shfl_xor_sync(0xffffffffu, v, o));
    return v;
}
__device__ __forceinline__ float elu1(float z){ return z > 0.f ? z + 1.f : expf(z); }
__device__ __forceinline__ float silu(float g){ return g / (1.f + expf(-g)); }

// C[tok][o] += sum_i aT[i][tok] * W[i][o]   (aT transposed tile in smem, 16 tokens)
__device__ __forceinline__ void mm16(const float* __restrict__ aT,
                                     const float* __restrict__ W,
                                     int o, float acc[16]){
#pragma unroll
    for (int r = 0; r < 16; r++) acc[r] = 0.f;
#pragma unroll 4
    for (int i = 0; i < 128; i++){
        float w = W[i*128 + o];
        const float4* ap = (const float4*)(aT + i*16);
        float4 a0 = ap[0], a1 = ap[1], a2 = ap[2], a3 = ap[3];
        acc[0]  += a0.x*w; acc[1]  += a0.y*w; acc[2]  += a0.z*w; acc[3]  += a0.w*w;
        acc[4]  += a1.x*w; acc[5]  += a1.y*w; acc[6]  += a1.z*w; acc[7]  += a1.w*w;
        acc[8]  += a2.x*w; acc[9]  += a2.y*w; acc[10] += a2.z*w; acc[11] += a2.w*w;
        acc[12] += a3.x*w; acc[13] += a3.y*w; acc[14] += a3.z*w; acc[15] += a3.w*w;
    }
}

// dual-output version (two D x D weight matrices, same activations)
__device__ __forceinline__ void mm16_dual(const float* __restrict__ aT,
                                          const float* __restrict__ W1,
                                          const float* __restrict__ W2,
                                          int o, float a1o[16], float a2o[16]){
#pragma unroll
    for (int r = 0; r < 16; r++){ a1o[r] = 0.f; a2o[r] = 0.f; }
#pragma unroll 2
    for (int i = 0; i < 128; i++){
        float w1 = W1[i*128 + o];
        float w2 = W2[i*128 + o];
        const float4* ap = (const float4*)(aT + i*16);
        float4 a0 = ap[0], a1 = ap[1], a2 = ap[2], a3 = ap[3];
        a1o[0]+=a0.x*w1; a1o[1]+=a0.y*w1; a1o[2]+=a0.z*w1; a1o[3]+=a0.w*w1;
        a1o[4]+=a1.x*w1; a1o[5]+=a1.y*w1; a1o[6]+=a1.z*w1; a1o[7]+=a1.w*w1;
        a1o[8]+=a2.x*w1; a1o[9]+=a2.y*w1; a1o[10]+=a2.z*w1; a1o[11]+=a2.w*w1;
        a1o[12]+=a3.x*w1; a1o[13]+=a3.y*w1; a1o[14]+=a3.z*w1; a1o[15]+=a3.w*w1;
        a2o[0]+=a0.x*w2; a2o[1]+=a0.y*w2; a2o[2]+=a0.z*w2; a2o[3]+=a0.w*w2;
        a2o[4]+=a1.x*w2; a2o[5]+=a1.y*w2; a2o[6]+=a1.z*w2; a2o[7]+=a1.w*w2;
        a2o[8]+=a2.x*w2; a2o[9]+=a2.y*w2; a2o[10]+=a2.z*w2; a2o[11]+=a2.w*w2;
        a2o[12]+=a3.x*w2; a2o[13]+=a3.y*w2; a2o[14]+=a3.z*w2; a2o[15]+=a3.w*w2;
    }
}

// ---------------- K1: rmsnorm #1 ----------------
__global__ void k_rms1(const float* __restrict__ x, const float* __restrict__ g1){
    int t = blockIdx.x*8 + (threadIdx.x >> 5);
    int l = threadIdx.x & 31;
    const float* xr = x + t*DD;
    float s = 0.f;
#pragma unroll
    for (int j = 0; j < 4; j++){ float v = xr[l + 32*j]; s += v*v; }
    s = warp_sum(s);
    float rinv = rsqrtf(s*(1.f/128.f) + EPS);
#pragma unroll
    for (int j = 0; j < 4; j++){ int i = l + 32*j; g_h1[t*DD + i] = g1[i]*xr[i]*rinv; }
}

// ---------------- K2: q / kd / kv projections (+elu+1) ----------------
__global__ void k_qkv(const float* __restrict__ qW,  const float* __restrict__ qb,
                      const float* __restrict__ kdW, const float* __restrict__ kdb,
                      const float* __restrict__ kuW, const float* __restrict__ kub){
    __shared__ __align__(16) float aT[128*16];
    __shared__ __align__(16) float kdT[32*16];
    int t0 = blockIdx.x*16;
    int o  = threadIdx.x;
#pragma unroll
    for (int r = 0; r < 16; r++) aT[o*16 + r] = g_h1[(t0+r)*DD + o];
    __syncthreads();

    // q = h1 @ qW + qb, elu+1
    {
        float acc[16];
        mm16(aT, qW, o, acc);
        float b = qb[o];
#pragma unroll
        for (int r = 0; r < 16; r++)
            g_q[(t0+r)*DD + o] = elu1(acc[r] + b);
    }
    // kd = h1 @ kdW + kdb  (32 outputs)
    if (o < 32){
        float acc[16];
#pragma unroll
        for (int r = 0; r < 16; r++) acc[r] = 0.f;
#pragma unroll 4
        for (int i = 0; i < 128; i++){
            float w = kdW[i*32 + o];
            const float4* ap = (const float4*)(aT + i*16);
            float4 a0 = ap[0], a1 = ap[1], a2 = ap[2], a3 = ap[3];
            acc[0]+=a0.x*w; acc[1]+=a0.y*w; acc[2]+=a0.z*w; acc[3]+=a0.w*w;
            acc[4]+=a1.x*w; acc[5]+=a1.y*w; acc[6]+=a1.z*w; acc[7]+=a1.w*w;
            acc[8]+=a2.x*w; acc[9]+=a2.y*w; acc[10]+=a2.z*w; acc[11]+=a2.w*w;
            acc[12]+=a3.x*w; acc[13]+=a3.y*w; acc[14]+=a3.z*w; acc[15]+=a3.w*w;
        }
        float b = kdb[o];
#pragma unroll
        for (int r = 0; r < 16; r++) kdT[o*16 + r] = acc[r] + b;
    }
    __syncthreads();

    // kv = kd @ kuW + kub : outputs o and o+128
    {
        float ac0[16], ac1[16];
#pragma unroll
        for (int r = 0; r < 16; r++){ ac0[r] = 0.f; ac1[r] = 0.f; }
#pragma unroll 4
        for (int i = 0; i < 32; i++){
            float w0 = kuW[i*256 + o];
            float w1 = kuW[i*256 + 128 + o];
            const float4* ap = (const float4*)(kdT + i*16);
            float4 a0 = ap[0], a1 = ap[1], a2 = ap[2], a3 = ap[3];
            ac0[0]+=a0.x*w0; ac0[1]+=a0.y*w0; ac0[2]+=a0.z*w0; ac0[3]+=a0.w*w0;
            ac0[4]+=a1.x*w0; ac0[5]+=a1.y*w0; ac0[6]+=a1.z*w0; ac0[7]+=a1.w*w0;
            ac0[8]+=a2.x*w0; ac0[9]+=a2.y*w0; ac0[10]+=a2.z*w0; ac0[11]+=a2.w*w0;
            ac0[12]+=a3.x*w0; ac0[13]+=a3.y*w0; ac0[14]+=a3.z*w0; ac0[15]+=a3.w*w0;
            ac1[0]+=a0.x*w1; ac1[1]+=a0.y*w1; ac1[2]+=a0.z*w1; ac1[3]+=a0.w*w1;
            ac1[4]+=a1.x*w1; ac1[5]+=a1.y*w1; ac1[6]+=a1.z*w1; ac1[7]+=a1.w*w1;
            ac1[8]+=a2.x*w1; ac1[9]+=a2.y*w1; ac1[10]+=a2.z*w1; ac1[11]+=a2.w*w1;
            ac1[12]+=a3.x*w1; ac1[13]+=a3.y*w1; ac1[14]+=a3.z*w1; ac1[15]+=a3.w*w1;
        }
        int hA = o >> 5, pA = o & 31;
        float bA = kub[o], bB = kub[o + 128];
#pragma unroll
        for (int r = 0; r < 16; r++){
            int t = t0 + r;
            float vA = ac0[r] + bA, vB = ac1[r] + bB;
            if (pA < 16){
                g_k[t*DD + hA*16 + pA]       = elu1(vA);
                g_k[t*DD + (hA+4)*16 + pA]   = elu1(vB);
            } else {
                g_v[t*DD + hA*16 + (pA-16)]     = vA;
                g_v[t*DD + (hA+4)*16 + (pA-16)] = vB;
            }
        }
    }
}

// ---------------- K3: context + ksum (one block per (b,h), deterministic) ----------------
__global__ void k_ctx(){
    int bh = blockIdx.x;
    int b = bh >> 3, h = bh & 7;
    int d = threadIdx.x >> 4, e = threadIdx.x & 15;
    const float* kp = g_k + (size_t)(b*TT)*DD + h*16 + d;
    const float* vp = g_v + (size_t)(b*TT)*DD + h*16 + e;
    float acc = 0.f, ks = 0.f;
#pragma unroll 8
    for (int t = 0; t < TT; t++){
        float kv_ = kp[t*DD];
        float vv  = vp[t*DD];
        acc += kv_ * vv;
        ks  += kv_;
    }
    g_ctx[bh*256 + d*16 + e] = acc;
    if (e == 0) g_ksum[bh*16 + d] = ks;
}

// ---------------- K4: z = 1/(q . k_sum + eps), per (token, head) ----------------
__global__ void k_z(){
    int idx = blockIdx.x*256 + threadIdx.x;   // t*8+h
    int t = idx >> 3, h = idx & 7, b = t >> 9;
    const float* qp = g_q + t*DD + h*16;
    const float* kp = g_ksum + (b*8 + h)*16;
    float s = 0.f;
#pragma unroll
    for (int d = 0; d < 16; d++) s += qp[d]*kp[d];
    g_z[idx] = 1.f/(s + EPS);
}

// ---------------- K5: fused attn -> oW -> rot -> turbo-quant -> swiglu -> residual -> rmsnorm2 ----------------
__global__ void k_fused(const float* __restrict__ oW,  const float* __restrict__ ob,
                        const float* __restrict__ rot, const float* __restrict__ tqs,
                        const float* __restrict__ s1W, const float* __restrict__ s1b,
                        const float* __restrict__ s2W, const float* __restrict__ s2b,
                        const float* __restrict__ x,   const float* __restrict__ g2){
    __shared__ __align__(16) float ctxs[2048];
    __shared__ __align__(16) float qs[16*128];
    __shared__ __align__(16) float tA[128*16];
    __shared__ __align__(16) float tB[128*16];
    __shared__ float zsh[128];
    __shared__ float mags[16];
    __shared__ float rinvs[16];
    int t0 = blockIdx.x*16;
    int b  = t0 >> 9;
    int o  = threadIdx.x;
    int h  = o >> 4, e = o & 15;
    int w  = o >> 5, l = o & 31;

#pragma unroll
    for (int r = 0; r < 16; r++){
        ctxs[r*128 + o] = g_ctx[b*2048 + r*128 + o];
        qs[r*128 + o]   = g_q[(t0+r)*DD + o];
    }
    zsh[o] = g_z[t0*8 + o];
    __syncthreads();

    // phase 1: attn[tok][h,e] = z * sum_d q[tok][h,d] * ctx[h][d][e]
    {
        float acc[16];
#pragma unroll
        for (int r = 0; r < 16; r++) acc[r] = 0.f;
#pragma unroll
        for (int d = 0; d < 16; d++){
            float c = ctxs[h*256 + d*16 + e];
#pragma unroll
            for (int r = 0; r < 16; r++) acc[r] += qs[r*128 + h*16 + d]*c;
        }
#pragma unroll
        for (int r = 0; r < 16; r++) tA[o*16 + r] = acc[r]*zsh[r*8 + h];
    }
    __syncthreads();

    // phase 2: mla = attn @ oW + ob  -> tB
    {
        float acc[16];
        mm16(tA, oW, o, acc);
        float bo = ob[o];
#pragma unroll
        for (int r = 0; r < 16; r++) tB[o*16 + r] = acc[r] + bo;
    }
    __syncthreads();

    // phase 3: y = mla @ rot -> tA
    {
        float acc[16];
        mm16(tB, rot, o, acc);
#pragma unroll
        for (int r = 0; r < 16; r++) tA[o*16 + r] = acc[r];
    }
    __syncthreads();

    // phase 4: per-token magnitude
#pragma unroll
    for (int tt = 0; tt < 4; tt++){
        int tok = w*4 + tt;
        float s = 0.f;
#pragma unroll
        for (int j = 0; j < 4; j++){ float v = tA[(l + 32*j)*16 + tok]; s += v*v; }
        s = warp_sum(s);
        if (l == 0) mags[tok] = sqrtf(s*(1.f/128.f) + EPS);
    }
    __syncthreads();

    // phase 5: turbo quant -> tB
    {
        float sc = tqs[o];
#pragma unroll
        for (int r = 0; r < 16; r++){
            float m  = mags[r];
            float ph = tA[o*16 + r] / m;
            ph = fminf(fmaxf(ph, -1.f), 1.f);
            tB[o*16 + r] = ph*m*sc;
        }
    }
    __syncthreads();

    // phase 6: swiglu(s1,s2) + residual -> g_x2, also stage x2 in tA
    {
        float ag[16], au[16];
        mm16_dual(tB, s1W, s2W, o, ag, au);
        float b1 = s1b[o], b2 = s2b[o];
#pragma unroll
        for (int r = 0; r < 16; r++){
            float g  = ag[r] + b1;
            float u  = au[r] + b2;
            float x2 = x[(t0+r)*DD + o] + silu(g)*u;
            g_x2[(t0+r)*DD + o] = x2;
            tA[o*16 + r] = x2;
        }
    }
    __syncthreads();

    // phase 7: rmsnorm #2
#pragma unroll
    for (int tt = 0; tt < 4; tt++){
        int tok = w*4 + tt;
        float s = 0.f;
#pragma unroll
        for (int j = 0; j < 4; j++){ float v = tA[(l + 32*j)*16 + tok]; s += v*v; }
        s = warp_sum(s);
        if (l == 0) rinvs[tok] = rsqrtf(s*(1.f/128.f) + EPS);
    }
    __syncthreads();
    {
        float gg = g2[o];
#pragma unroll
        for (int r = 0; r < 16; r++)
            g_h2[(t0+r)*DD + o] = gg * tA[o*16 + r] * rinvs[r];
    }
}

// ---------------- K6: gate logits -> softmax -> top2 ----------------
__device__ __forceinline__ void top2_merge(float& v1, int& i1, float& v2, int& i2,
                                           float v, int i){
    if (v > v1 || (v == v1 && i < i1)){ v2 = v1; i2 = i1; v1 = v; i1 = i; }
    else if (v > v2 || (v == v2 && i < i2)){ v2 = v; i2 = i; }
}

__global__ void k_gate(const float* __restrict__ gateW, const float* __restrict__ gateb){
    __shared__ __align__(16) float aT[128*16];
    __shared__ float lg[16*256];
    int t0 = blockIdx.x*16;
    int o  = threadIdx.x;
#pragma unroll
    for (int r = 0; r < 16; r++) aT[o*16 + r] = g_h2[(t0+r)*DD + o];
    __syncthreads();
    {
        float a0[16], a1[16];
#pragma unroll
        for (int r = 0; r < 16; r++){ a0[r] = 0.f; a1[r] = 0.f; }
#pragma unroll 2
        for (int i = 0; i < 128; i++){
            float w0 = gateW[i*256 + o];
            float w1 = gateW[i*256 + 128 + o];
            const float4* ap = (const float4*)(aT + i*16);
            float4 q0 = ap[0], q1 = ap[1], q2 = ap[2], q3 = ap[3];
            a0[0]+=q0.x*w0; a0[1]+=q0.y*w0; a0[2]+=q0.z*w0; a0[3]+=q0.w*w0;
            a0[4]+=q1.x*w0; a0[5]+=q1.y*w0; a0[6]+=q1.z*w0; a0[7]+=q1.w*w0;
            a0[8]+=q2.x*w0; a0[9]+=q2.y*w0; a0[10]+=q2.z*w0; a0[11]+=q2.w*w0;
            a0[12]+=q3.x*w0; a0[13]+=q3.y*w0; a0[14]+=q3.z*w0; a0[15]+=q3.w*w0;
            a1[0]+=q0.x*w1; a1[1]+=q0.y*w1; a1[2]+=q0.z*w1; a1[3]+=q0.w*w1;
            a1[4]+=q1.x*w1; a1[5]+=q1.y*w1; a1[6]+=q1.z*w1; a1[7]+=q1.w*w1;
            a1[8]+=q2.x*w1; a1[9]+=q2.y*w1; a1[10]+=q2.z*w1; a1[11]+=q2.w*w1;
            a1[12]+=q3.x*w1; a1[13]+=q3.y*w1; a1[14]+=q3.z*w1; a1[15]+=q3.w*w1;
        }
        float b0 = gateb[o], b1 = gateb[o + 128];
#pragma unroll
        for (int r = 0; r < 16; r++){
            lg[r*256 + o]       = a0[r] + b0;
            lg[r*256 + 128 + o] = a1[r] + b1;
        }
    }
    __syncthreads();

    int w = o >> 5, l = o & 31;
#pragma unroll
    for (int tt = 0; tt < 4; tt++){
        int tok = w*4 + tt;
        const float* row = lg + tok*256;
        float mx = -3.4e38f;
#pragma unroll
        for (int j = 0; j < 8; j++) mx = fmaxf(mx, row[l + 32*j]);
        mx = warp_max(mx);
        float sum = 0.f;
        float v1 = -3.4e38f, v2 = -3.4e38f; int i1 = 0x7fffffff, i2 = 0x7fffffff;
#pragma unroll
        for (int j = 0; j < 8; j++){
            int idx = l + 32*j;
            float v = row[idx];
            sum += expf(v - mx);
            top2_merge(v1, i1, v2, i2, v, idx);
        }
        sum = warp_sum(sum);
#pragma unroll
        for (int off = 16; off > 0; off >>= 1){
            float ov1 = __shfl_xor_sync(0xffffffffu, v1, off);
            int   oi1 = __shfl_xor_sync(0xffffffffu, i1, off);
            float ov2 = __shfl_xor_sync(0xffffffffu, v2, off);
            int   oi2 = __shfl_xor_sync(0xffffffffu, i2, off);
            top2_merge(v1, i1, v2, i2, ov1, oi1);
            top2_merge(v1, i1, v2, i2, ov2, oi2);
        }
        if (l == 0){
            int t = t0 + tok;
            float p1 = expf(v1 - mx)/sum;
            float p2 = expf(v2 - mx)/sum;
            float den = p1 + p2 + EPS;
            g_eidx[2*t]   = i1;
            g_eidx[2*t+1] = i2;
            g_ew[2*t]     = p1/den;
            g_ew[2*t+1]   = p2/den;
        }
    }
}

// ---------------- K7: top-2 expert matvecs + weighted avg ----------------
__global__ void k_moe_a(const float* __restrict__ expW){
    __shared__ float hs[128];
    int t = blockIdx.x;
    int o = threadIdx.x;
    hs[o] = g_h2[t*DD + o];
    int e1 = g_eidx[2*t], e2 = g_eidx[2*t+1];
    float w1 = g_ew[2*t], w2 = g_ew[2*t+1];
    __syncthreads();
    const float* W1 = expW + (size_t)e1*16384 + o;
    const float* W2 = expW + (size_t)e2*16384 + o;
    float a1 = 0.f, a2 = 0.f;
#pragma unroll 8
    for (int i = 0; i < 128; i++){
        float a = hs[i];
        a1 += a*W1[i*128];
        a2 += a*W2[i*128];
    }
    g_y[t*256 + o]       = a1;
    g_y[t*256 + 128 + o] = a2;
    g_wavg[t*DD + o]     = w1*a1 + w2*a2;
}

// ---------------- K8: swiglu(m1,m2) + residual + wvar/consensus ----------------
__global__ void k_moe_b(const float* __restrict__ m1W, const float* __restrict__ m1b,
                        const float* __restrict__ m2W, const float* __restrict__ m2b,
                        float* __restrict__ out, float* __restrict__ cons){
    __shared__ __align__(16) float aT[128*16];
    __shared__ __align__(16) float wvT[128*16];
    __shared__ float ews[32];
    int t0 = blockIdx.x*16;
    int o  = threadIdx.x;
#pragma unroll
    for (int r = 0; r < 16; r++) aT[o*16 + r] = g_wavg[(t0+r)*DD + o];
    if (o < 32) ews[o] = g_ew[t0*2 + o];
    __syncthreads();

    float ag[16], au[16];
    mm16_dual(aT, m1W, m2W, o, ag, au);
    float b1 = m1b[o], b2 = m2b[o];
#pragma unroll
    for (int r = 0; r < 16; r++){
        int t = t0 + r;
        float g  = ag[r] + b1;
        float u  = au[r] + b2;
        float ws = silu(g)*u;
        out[t*DD + o] = g_x2[t*DD + o] + ws;
        float w1 = ews[2*r], w2 = ews[2*r+1];
        float y1 = g_y[t*256 + o];
        float y2 = g_y[t*256 + 128 + o];
        float d1 = y1 - ws, d2 = y2 - ws;
        wvT[o*16 + r] = w1*d1*d1 + w2*d2*d2;
    }
    __syncthreads();

    int w = o >> 5, l = o & 31;
#pragma unroll
    for (int tt = 0; tt < 4; tt++){
        int tok = w*4 + tt;
        float s = 0.f;
#pragma unroll
        for (int j = 0; j < 4; j++) s += wvT[(l + 32*j)*16 + tok];
        s = warp_sum(s);
        if (l == 0) cons[t0 + tok] = expf(-s*(1.f/128.f));
    }
}

// ---------------- launch ----------------
extern "C" void kernel_launch(void* const* d_in, const int* in_sizes, int n_in,
                              void* d_out, int out_size){
    const float* x    = (const float*)d_in[0];
    const float* g1   = (const float*)d_in[1];
    const float* qW   = (const float*)d_in[2];
    const float* qb   = (const float*)d_in[3];
    const float* kdW  = (const float*)d_in[4];
    const float* kdb  = (const float*)d_in[5];
    const float* kuW  = (const float*)d_in[6];
    const float* kub  = (const float*)d_in[7];
    const float* oW   = (const float*)d_in[8];
    const float* ob   = (const float*)d_in[9];
    const float* rot  = (const float*)d_in[10];
    const float* tqs  = (const float*)d_in[11];
    const float* s1W  = (const float*)d_in[12];
    const float* s1b  = (const float*)d_in[13];
    const float* s2W  = (const float*)d_in[14];
    const float* s2b  = (const float*)d_in[15];
    const float* g2   = (const float*)d_in[16];
    const float* gateW= (const float*)d_in[17];
    const float* gateb= (const float*)d_in[18];
    const float* expW = (const float*)d_in[19];
    const float* m1W  = (const float*)d_in[20];
    const float* m1b  = (const float*)d_in[21];
    const float* m2W  = (const float*)d_in[22];
    const float* m2b  = (const float*)d_in[23];

    float* out  = (float*)d_out;
    float* cons = out + (size_t)NT*DD;

    k_rms1 <<<NT/8, 256>>>(x, g1);
    k_qkv  <<<NT/16, 128>>>(qW, qb, kdW, kdb, kuW, kub);
    k_ctx  <<<BB*HH, 256>>>();
    k_z    <<<NT*HH/256, 256>>>();
    k_fused<<<NT/16, 128>>>(oW, ob, rot, tqs, s1W, s1b, s2W, s2b, x, g2);
    k_gate <<<NT/16, 128>>>(gateW, gateb);
    k_moe_a<<<NT, 128>>>(expW);
    k_moe_b<<<NT/16, 128>>>(m1W, m1b, m2W, m2b, out, cons);
}

// round 4
// speedup vs baseline: 1.1903x; 1.1903x over previous
#include <cuda_runtime.h>
#include <math.h>

#define NT 2048      // B*T tokens
#define DD 128       // d_model
#define TT 512
#define BB 4
#define HH 8
#define EE 256
#define EPS 1e-6f
#define MAXB 4096    // bin capacity per expert (worst case)

// ---------------- scratch (device globals: allocation-free) ----------------
__device__ float g_q [NT*DD];
__device__ float g_k [NT*DD];
__device__ float g_v [NT*DD];
__device__ float g_ctxp [4*32*256];    // [part][bh][d*16+e]
__device__ float g_ksump[4*32*16];     // [part][bh][d]
__device__ float g_x2[NT*DD];
__device__ float g_h2[NT*DD];
__device__ float g_y [NT*256];         // [t][slot][128]
__device__ float g_ew[NT*2];
__device__ int   g_cnt[EE];
__device__ int   g_bin[EE*MAXB];       // packed t*2+slot

// ---------------- helpers ----------------
__device__ __forceinline__ float warp_sum(float v){
#pragma unroll
    for (int o = 16; o > 0; o >>= 1) v += __shfl_xor_sync(0xffffffffu, v, o);
    return v;
}
__device__ __forceinline__ float warp_max(float v){
#pragma unroll
    for (int o = 16; o > 0; o >>= 1) v = fmaxf(v, __shfl_xor_sync(0xffffffffu, v, o));
    return v;
}
__device__ __forceinline__ float elu1(float z){ return z > 0.f ? z + 1.f : expf(z); }
__device__ __forceinline__ float silu(float g){ return g / (1.f + expf(-g)); }

// split-K half matmul: acc[r] = sum_{i in [g*64,(g+1)*64)} aT[i][r] * W[i*128+o]
__device__ __forceinline__ void mm16h(const float* __restrict__ aT,
                                      const float* __restrict__ W,
                                      int o, int g, float acc[16]){
#pragma unroll
    for (int r = 0; r < 16; r++) acc[r] = 0.f;
    const float*  Wp = W + (size_t)(g*64)*128 + o;
    const float4* ap = (const float4*)(aT + (g*64)*16);
#pragma unroll 4
    for (int i = 0; i < 64; i++){
        float w = Wp[i*128];
        float4 a0 = ap[i*4+0], a1 = ap[i*4+1], a2 = ap[i*4+2], a3 = ap[i*4+3];
        acc[0]+=a0.x*w; acc[1]+=a0.y*w; acc[2]+=a0.z*w; acc[3]+=a0.w*w;
        acc[4]+=a1.x*w; acc[5]+=a1.y*w; acc[6]+=a1.z*w; acc[7]+=a1.w*w;
        acc[8]+=a2.x*w; acc[9]+=a2.y*w; acc[10]+=a2.z*w; acc[11]+=a2.w*w;
        acc[12]+=a3.x*w; acc[13]+=a3.y*w; acc[14]+=a3.z*w; acc[15]+=a3.w*w;
    }
}

__device__ __forceinline__ void mm16h_dual(const float* __restrict__ aT,
                                           const float* __restrict__ W1,
                                           const float* __restrict__ W2,
                                           int o, int g, float a1o[16], float a2o[16]){
#pragma unroll
    for (int r = 0; r < 16; r++){ a1o[r]=0.f; a2o[r]=0.f; }
    const float*  W1p = W1 + (size_t)(g*64)*128 + o;
    const float*  W2p = W2 + (size_t)(g*64)*128 + o;
    const float4* ap  = (const float4*)(aT + (g*64)*16);
#pragma unroll 2
    for (int i = 0; i < 64; i++){
        float w1 = W1p[i*128];
        float w2 = W2p[i*128];
        float4 a0 = ap[i*4+0], a1 = ap[i*4+1], a2 = ap[i*4+2], a3 = ap[i*4+3];
        a1o[0]+=a0.x*w1; a1o[1]+=a0.y*w1; a1o[2]+=a0.z*w1; a1o[3]+=a0.w*w1;
        a1o[4]+=a1.x*w1; a1o[5]+=a1.y*w1; a1o[6]+=a1.z*w1; a1o[7]+=a1.w*w1;
        a1o[8]+=a2.x*w1; a1o[9]+=a2.y*w1; a1o[10]+=a2.z*w1; a1o[11]+=a2.w*w1;
        a1o[12]+=a3.x*w1; a1o[13]+=a3.y*w1; a1o[14]+=a3.z*w1; a1o[15]+=a3.w*w1;
        a2o[0]+=a0.x*w2; a2o[1]+=a0.y*w2; a2o[2]+=a0.z*w2; a2o[3]+=a0.w*w2;
        a2o[4]+=a1.x*w2; a2o[5]+=a1.y*w2; a2o[6]+=a1.z*w2; a2o[7]+=a1.w*w2;
        a2o[8]+=a2.x*w2; a2o[9]+=a2.y*w2; a2o[10]+=a2.z*w2; a2o[11]+=a2.w*w2;
        a2o[12]+=a3.x*w2; a2o[13]+=a3.y*w2; a2o[14]+=a3.z*w2; a2o[15]+=a3.w*w2;
    }
}

// ---------------- K1: rmsnorm1 + q/kd/kv projections (fused, 256 thr split-K) ----------------
__global__ void k_pre(const float* __restrict__ x,   const float* __restrict__ g1,
                      const float* __restrict__ qW,  const float* __restrict__ qb,
                      const float* __restrict__ kdW, const float* __restrict__ kdb,
                      const float* __restrict__ kuW, const float* __restrict__ kub){
    __shared__ __align__(16) float aT [128*16];
    __shared__ __align__(16) float red[128*16];
    __shared__ __align__(16) float kdT[32*16];
    int tid = threadIdx.x;
    int c = tid & 127, g = tid >> 7;
    int w = tid >> 5,  l = tid & 31;
    int t0 = blockIdx.x*16;

    // zero MoE bin counters once (block 0)
    if (blockIdx.x == 0) g_cnt[tid & 255] = 0;

    // rmsnorm: warp w handles tokens w*2, w*2+1
#pragma unroll
    for (int tt = 0; tt < 2; tt++){
        int tok = w*2 + tt;
        const float* xr = x + (size_t)(t0+tok)*DD;
        float s = 0.f;
#pragma unroll
        for (int j = 0; j < 4; j++){ float v = xr[l+32*j]; s += v*v; }
        s = warp_sum(s);
        float rinv = rsqrtf(s*(1.f/128.f) + EPS);
#pragma unroll
        for (int j = 0; j < 4; j++){
            int i = l + 32*j;
            aT[i*16 + tok] = g1[i]*xr[i]*rinv;
        }
    }
    __syncthreads();

    // q = h1 @ qW + qb, elu+1   (split-K)
    {
        float acc[16];
        mm16h(aT, qW, c, g, acc);
        if (g){
#pragma unroll
            for (int r = 0; r < 16; r++) red[c*16+r] = acc[r];
        }
        __syncthreads();
        if (!g){
            float b = qb[c];
#pragma unroll
            for (int r = 0; r < 16; r++)
                g_q[(size_t)(t0+r)*DD + c] = elu1(acc[r] + red[c*16+r] + b);
        }
        __syncthreads();
    }

    // kd = h1 @ kdW + kdb  (32 outputs, split-K)
    {
        float acc[16];
#pragma unroll
        for (int r = 0; r < 16; r++) acc[r] = 0.f;
        if (c < 32){
            const float*  Wp = kdW + (size_t)(g*64)*32 + c;
            const float4* ap = (const float4*)(aT + (g*64)*16);
#pragma unroll 4
            for (int i = 0; i < 64; i++){
                float wv = Wp[i*32];
                float4 a0 = ap[i*4+0], a1 = ap[i*4+1], a2 = ap[i*4+2], a3 = ap[i*4+3];
                acc[0]+=a0.x*wv; acc[1]+=a0.y*wv; acc[2]+=a0.z*wv; acc[3]+=a0.w*wv;
                acc[4]+=a1.x*wv; acc[5]+=a1.y*wv; acc[6]+=a1.z*wv; acc[7]+=a1.w*wv;
                acc[8]+=a2.x*wv; acc[9]+=a2.y*wv; acc[10]+=a2.z*wv; acc[11]+=a2.w*wv;
                acc[12]+=a3.x*wv; acc[13]+=a3.y*wv; acc[14]+=a3.z*wv; acc[15]+=a3.w*wv;
            }
        }
        if (g && c < 32){
#pragma unroll
            for (int r = 0; r < 16; r++) red[c*16+r] = acc[r];
        }
        __syncthreads();
        if (!g && c < 32){
            float b = kdb[c];
#pragma unroll
            for (int r = 0; r < 16; r++) kdT[c*16+r] = acc[r] + red[c*16+r] + b;
        }
        __syncthreads();
    }

    // kv = kd @ kuW + kub : 256 outputs, one per thread, full K=32
    {
        int oo = tid;
        float acc[16];
#pragma unroll
        for (int r = 0; r < 16; r++) acc[r] = 0.f;
        const float*  Wp = kuW + oo;
        const float4* ap = (const float4*)kdT;
#pragma unroll 4
        for (int i = 0; i < 32; i++){
            float wv = Wp[i*256];
            float4 a0 = ap[i*4+0], a1 = ap[i*4+1], a2 = ap[i*4+2], a3 = ap[i*4+3];
            acc[0]+=a0.x*wv; acc[1]+=a0.y*wv; acc[2]+=a0.z*wv; acc[3]+=a0.w*wv;
            acc[4]+=a1.x*wv; acc[5]+=a1.y*wv; acc[6]+=a1.z*wv; acc[7]+=a1.w*wv;
            acc[8]+=a2.x*wv; acc[9]+=a2.y*wv; acc[10]+=a2.z*wv; acc[11]+=a2.w*wv;
            acc[12]+=a3.x*wv; acc[13]+=a3.y*wv; acc[14]+=a3.z*wv; acc[15]+=a3.w*wv;
        }
        int h = oo >> 5, p = oo & 31;
        float b = kub[oo];
#pragma unroll
        for (int r = 0; r < 16; r++){
            size_t t = t0 + r;
            float v = acc[r] + b;
            if (p < 16) g_k[t*DD + h*16 + p]        = elu1(v);
            else        g_v[t*DD + h*16 + (p-16)]   = v;
        }
    }
}

// ---------------- K2: partial context + ksum (4 T-partitions per (b,h)) ----------------
__global__ void k_ctx(){
    int bh = blockIdx.x >> 2, part = blockIdx.x & 3;
    int b = bh >> 3, h = bh & 7;
    int d = threadIdx.x >> 4, e = threadIdx.x & 15;
    const float* kp = g_k + ((size_t)(b*TT) + part*128)*DD + h*16 + d;
    const float* vp = g_v + ((size_t)(b*TT) + part*128)*DD + h*16 + e;
    float acc = 0.f, ks = 0.f;
#pragma unroll 8
    for (int t = 0; t < 128; t++){
        float kv_ = kp[t*DD];
        float vv  = vp[t*DD];
        acc += kv_ * vv;
        ks  += kv_;
    }
    g_ctxp[(part*32 + bh)*256 + d*16 + e] = acc;
    if (e == 0) g_ksump[(part*32 + bh)*16 + d] = ks;
}

// ---------------- top2 merge ----------------
__device__ __forceinline__ void top2_merge(float& v1, int& i1, float& v2, int& i2,
                                           float v, int i){
    if (v > v1 || (v == v1 && i < i1)){ v2 = v1; i2 = i1; v1 = v; i1 = i; }
    else if (v > v2 || (v == v2 && i < i2)){ v2 = v; i2 = i; }
}

// ---------------- K3: attn -> z -> oW -> rot -> TQ -> swiglu -> resid -> rms2 -> gate -> top2 -> bin ----------------
__global__ void k_fused(const float* __restrict__ oW,  const float* __restrict__ ob,
                        const float* __restrict__ rot, const float* __restrict__ tqs,
                        const float* __restrict__ s1W, const float* __restrict__ s1b,
                        const float* __restrict__ s2W, const float* __restrict__ s2b,
                        const float* __restrict__ x,   const float* __restrict__ g2,
                        const float* __restrict__ gateW, const float* __restrict__ gateb){
    __shared__ __align__(16) float u  [4096];  // ctx[2048]+q[2048], later gate logits [16][256]
    __shared__ __align__(16) float tA [2048];
    __shared__ __align__(16) float tB [2048];
    __shared__ __align__(16) float red[2048];
    __shared__ float zsh[128], ksum_sh[128], mags[16], rinvs[16];
    int tid = threadIdx.x;
    int c = tid & 127, g = tid >> 7;
    int w = tid >> 5,  l = tid & 31;
    int t0 = blockIdx.x*16, b = t0 >> 9;

    // load ctx (reduce 4 parts) and q tile
#pragma unroll
    for (int j = 0; j < 8; j++){
        int q = tid + 256*j;
        float s = 0.f;
#pragma unroll
        for (int p = 0; p < 4; p++) s += g_ctxp[p*8192 + b*2048 + q];
        u[q] = s;
        u[2048 + q] = g_q[(size_t)t0*DD + q];
    }
    if (!g){
        float s = 0.f;
#pragma unroll
        for (int p = 0; p < 4; p++) s += g_ksump[p*512 + b*128 + c];
        ksum_sh[c] = s;
    }
    __syncthreads();

    // z per (tok, head)
    if (!g){
        int tok = c >> 3, h = c & 7;
        float s = 0.f;
#pragma unroll
        for (int d = 0; d < 16; d++) s += u[2048 + tok*128 + h*16 + d]*ksum_sh[h*16 + d];
        zsh[c] = 1.f/(s + EPS);
    }
    __syncthreads();

    // attn: out[tok][h*16+e]; thread (c,g): col c, tokens g*8..g*8+7
    {
        int h = c >> 4, e = c & 15;
        float acc[8];
#pragma unroll
        for (int r = 0; r < 8; r++) acc[r] = 0.f;
#pragma unroll
        for (int d = 0; d < 16; d++){
            float cv = u[h*256 + d*16 + e];
#pragma unroll
            for (int r = 0; r < 8; r++) acc[r] += u[2048 + (g*8+r)*128 + h*16 + d]*cv;
        }
#pragma unroll
        for (int r = 0; r < 8; r++) tA[c*16 + g*8 + r] = acc[r]*zsh[(g*8+r)*8 + h];
    }
    __syncthreads();

    // oW: tA -> tB
    {
        float acc[16];
        mm16h(tA, oW, c, g, acc);
        if (g){
#pragma unroll
            for (int r = 0; r < 16; r++) red[c*16+r] = acc[r];
        }
        __syncthreads();
        if (!g){
            float bo = ob[c];
#pragma unroll
            for (int r = 0; r < 16; r++) tB[c*16+r] = acc[r] + red[c*16+r] + bo;
        }
        __syncthreads();
    }

    // rot: tB -> tA
    {
        float acc[16];
        mm16h(tB, rot, c, g, acc);
        if (g){
#pragma unroll
            for (int r = 0; r < 16; r++) red[c*16+r] = acc[r];
        }
        __syncthreads();
        if (!g){
#pragma unroll
            for (int r = 0; r < 16; r++) tA[c*16+r] = acc[r] + red[c*16+r];
        }
        __syncthreads();
    }

    // magnitudes per token
#pragma unroll
    for (int tt = 0; tt < 2; tt++){
        int tok = w*2 + tt;
        float s = 0.f;
#pragma unroll
        for (int j = 0; j < 4; j++){ float v = tA[(l+32*j)*16 + tok]; s += v*v; }
        s = warp_sum(s);
        if (l == 0) mags[tok] = sqrtf(s*(1.f/128.f) + EPS);
    }
    __syncthreads();

    // turbo quant: tA -> tB
#pragma unroll
    for (int j = 0; j < 8; j++){
        int q = tid + 256*j;
        int r = q & 15, o = q >> 4;
        float m  = mags[r];
        float ph = tA[q]/m;
        ph = fminf(fmaxf(ph, -1.f), 1.f);
        tB[q] = ph*m*tqs[o];
    }
    __syncthreads();

    // swiglu(s1,s2) + residual: tB -> x2 in tA + g_x2 (staged dual reduction)
    {
        float ag[16], au[16];
        mm16h_dual(tB, s1W, s2W, c, g, ag, au);
        if (g){
#pragma unroll
            for (int r = 0; r < 16; r++) red[c*16+r] = ag[r];
        }
        __syncthreads();
        if (!g){
#pragma unroll
            for (int r = 0; r < 16; r++) ag[r] += red[c*16+r];
        }
        __syncthreads();
        if (g){
#pragma unroll
            for (int r = 0; r < 16; r++) red[c*16+r] = au[r];
        }
        __syncthreads();
        if (!g){
            float b1 = s1b[c], b2 = s2b[c];
#pragma unroll
            for (int r = 0; r < 16; r++){
                float gg = ag[r] + b1;
                float uu = au[r] + red[c*16+r] + b2;
                float x2 = x[(size_t)(t0+r)*DD + c] + silu(gg)*uu;
                g_x2[(size_t)(t0+r)*DD + c] = x2;
                tA[c*16+r] = x2;
            }
        }
        __syncthreads();
    }

    // rmsnorm2
#pragma unroll
    for (int tt = 0; tt < 2; tt++){
        int tok = w*2 + tt;
        float s = 0.f;
#pragma unroll
        for (int j = 0; j < 4; j++){ float v = tA[(l+32*j)*16 + tok]; s += v*v; }
        s = warp_sum(s);
        if (l == 0) rinvs[tok] = rsqrtf(s*(1.f/128.f) + EPS);
    }
    __syncthreads();
    if (!g){
        float gg = g2[c];
#pragma unroll
        for (int r = 0; r < 16; r++){
            float h2 = gg * tA[c*16+r] * rinvs[r];
            g_h2[(size_t)(t0+r)*DD + c] = h2;
            tB[c*16+r] = h2;
        }
    }
    __syncthreads();

    // gate: 256 outputs, one per thread, full K
    {
        int oo = tid;
        float acc[16];
#pragma unroll
        for (int r = 0; r < 16; r++) acc[r] = 0.f;
        const float*  Wp = gateW + oo;
        const float4* ap = (const float4*)tB;
#pragma unroll 2
        for (int i = 0; i < 128; i++){
            float wv = Wp[i*256];
            float4 a0 = ap[i*4+0], a1 = ap[i*4+1], a2 = ap[i*4+2], a3 = ap[i*4+3];
            acc[0]+=a0.x*wv; acc[1]+=a0.y*wv; acc[2]+=a0.z*wv; acc[3]+=a0.w*wv;
            acc[4]+=a1.x*wv; acc[5]+=a1.y*wv; acc[6]+=a1.z*wv; acc[7]+=a1.w*wv;
            acc[8]+=a2.x*wv; acc[9]+=a2.y*wv; acc[10]+=a2.z*wv; acc[11]+=a2.w*wv;
            acc[12]+=a3.x*wv; acc[13]+=a3.y*wv; acc[14]+=a3.z*wv; acc[15]+=a3.w*wv;
        }
        float bb = gateb[oo];
#pragma unroll
        for (int r = 0; r < 16; r++) u[r*256 + oo] = acc[r] + bb;
    }
    __syncthreads();

    // softmax + top2 + binning: 8 warps, 2 tokens each
#pragma unroll
    for (int tt = 0; tt < 2; tt++){
        int tok = w*2 + tt;
        const float* row = u + tok*256;
        float mx = -3.4e38f;
#pragma unroll
        for (int j = 0; j < 8; j++) mx = fmaxf(mx, row[l + 32*j]);
        mx = warp_max(mx);
        float sum = 0.f;
        float v1 = -3.4e38f, v2 = -3.4e38f; int i1 = 0x7fffffff, i2 = 0x7fffffff;
#pragma unroll
        for (int j = 0; j < 8; j++){
            int idx = l + 32*j;
            float v = row[idx];
            sum += expf(v - mx);
            top2_merge(v1, i1, v2, i2, v, idx);
        }
        sum = warp_sum(sum);
#pragma unroll
        for (int off = 16; off > 0; off >>= 1){
            float ov1 = __shfl_xor_sync(0xffffffffu, v1, off);
            int   oi1 = __shfl_xor_sync(0xffffffffu, i1, off);
            float ov2 = __shfl_xor_sync(0xffffffffu, v2, off);
            int   oi2 = __shfl_xor_sync(0xffffffffu, i2, off);
            top2_merge(v1, i1, v2, i2, ov1, oi1);
            top2_merge(v1, i1, v2, i2, ov2, oi2);
        }
        if (l == 0){
            int t = t0 + tok;
            float p1 = expf(v1 - mx)/sum;
            float p2 = expf(v2 - mx)/sum;
            float den = p1 + p2 + EPS;
            g_ew[2*t]   = p1/den;
            g_ew[2*t+1] = p2/den;
            int s1 = atomicAdd(&g_cnt[i1], 1);
            g_bin[i1*MAXB + s1] = 2*t;
            int s2 = atomicAdd(&g_cnt[i2], 1);
            g_bin[i2*MAXB + s2] = 2*t + 1;
        }
    }
}

// ---------------- K4: binned expert matvecs (one block per expert) ----------------
__global__ void k_moe(const float* __restrict__ expW){
    __shared__ __align__(16) float hs[16*128];
    __shared__ int toks[16];
    int e = blockIdx.x, o = threadIdx.x;
    int n = g_cnt[e];
    const float* We = expW + (size_t)e*16384;
    for (int c0 = 0; c0 < n; c0 += 16){
        int m = min(16, n - c0);
        if (o < 16) toks[o] = g_bin[e*MAXB + c0 + ((o < m) ? o : 0)];
        __syncthreads();
#pragma unroll
        for (int r = 0; r < 16; r++)
            hs[r*128 + o] = g_h2[(size_t)(toks[r] >> 1)*DD + o];
        __syncthreads();
        float acc[16];
#pragma unroll
        for (int r = 0; r < 16; r++) acc[r] = 0.f;
        const float* Wp = We + o;
#pragma unroll 2
        for (int i4 = 0; i4 < 32; i4++){
            float w0 = Wp[(i4*4+0)*128];
            float w1 = Wp[(i4*4+1)*128];
            float w2 = Wp[(i4*4+2)*128];
            float w3 = Wp[(i4*4+3)*128];
#pragma unroll
            for (int r = 0; r < 16; r++){
                float4 h4 = ((const float4*)(hs + r*128))[i4];
                acc[r] += h4.x*w0 + h4.y*w1 + h4.z*w2 + h4.w*w3;
            }
        }
        for (int r = 0; r < m; r++){
            int pk = toks[r];
            g_y[(size_t)(pk >> 1)*256 + (pk & 1)*128 + o] = acc[r];
        }
        __syncthreads();
    }
}

// ---------------- K5: wavg -> swiglu(m1,m2) -> residual + consensus ----------------
__global__ void k_moe_b(const float* __restrict__ m1W, const float* __restrict__ m1b,
                        const float* __restrict__ m2W, const float* __restrict__ m2b,
                        float* __restrict__ out, float* __restrict__ cons){
    __shared__ __align__(16) float aT [2048];
    __shared__ __align__(16) float red[2048];
    __shared__ float ews[32];
    int tid = threadIdx.x;
    int c = tid & 127, g = tid >> 7;
    int w = tid >> 5,  l = tid & 31;
    int t0 = blockIdx.x*16;

    if (tid < 32) ews[tid] = g_ew[t0*2 + tid];
#pragma unroll
    for (int j = 0; j < 8; j++){
        int q = tid + 256*j;
        int r = q & 15, o = q >> 4;
        size_t t = t0 + r;
        aT[q] = g_ew[2*t]*g_y[t*256 + o] + g_ew[2*t+1]*g_y[t*256 + 128 + o];
    }
    __syncthreads();

    float ag[16], au[16];
    mm16h_dual(aT, m1W, m2W, c, g, ag, au);
    if (g){
#pragma unroll
        for (int r = 0; r < 16; r++) red[c*16+r] = ag[r];
    }
    __syncthreads();
    if (!g){
#pragma unroll
        for (int r = 0; r < 16; r++) ag[r] += red[c*16+r];
    }
    __syncthreads();
    if (g){
#pragma unroll
        for (int r = 0; r < 16; r++) red[c*16+r] = au[r];
    }
    __syncthreads();
    if (!g){
        float b1 = m1b[c], b2 = m2b[c];
#pragma unroll
        for (int r = 0; r < 16; r++){
            size_t t = t0 + r;
            float gg = ag[r] + b1;
            float uu = au[r] + red[c*16+r] + b2;
            float ws = silu(gg)*uu;
            out[t*DD + c] = g_x2[t*DD + c] + ws;
            float w1 = ews[2*r], w2 = ews[2*r+1];
            float y1 = g_y[t*256 + c];
            float y2 = g_y[t*256 + 128 + c];
            float d1 = y1 - ws, d2 = y2 - ws;
            red[c*16+r] = w1*d1*d1 + w2*d2*d2;   // reuse red as wvar tile
        }
    }
    __syncthreads();

#pragma unroll
    for (int tt = 0; tt < 2; tt++){
        int tok = w*2 + tt;
        float s = 0.f;
#pragma unroll
        for (int j = 0; j < 4; j++) s += red[(l+32*j)*16 + tok];
        s = warp_sum(s);
        if (l == 0) cons[t0 + tok] = expf(-s*(1.f/128.f));
    }
}

// ---------------- launch ----------------
extern "C" void kernel_launch(void* const* d_in, const int* in_sizes, int n_in,
                              void* d_out, int out_size){
    const float* x    = (const float*)d_in[0];
    const float* g1   = (const float*)d_in[1];
    const float* qW   = (const float*)d_in[2];
    const float* qb   = (const float*)d_in[3];
    const float* kdW  = (const float*)d_in[4];
    const float* kdb  = (const float*)d_in[5];
    const float* kuW  = (const float*)d_in[6];
    const float* kub  = (const float*)d_in[7];
    const float* oW   = (const float*)d_in[8];
    const float* ob   = (const float*)d_in[9];
    const float* rot  = (const float*)d_in[10];
    const float* tqs  = (const float*)d_in[11];
    const float* s1W  = (const float*)d_in[12];
    const float* s1b  = (const float*)d_in[13];
    const float* s2W  = (const float*)d_in[14];
    const float* s2b  = (const float*)d_in[15];
    const float* g2   = (const float*)d_in[16];
    const float* gateW= (const float*)d_in[17];
    const float* gateb= (const float*)d_in[18];
    const float* expW = (const float*)d_in[19];
    const float* m1W  = (const float*)d_in[20];
    const float* m1b  = (const float*)d_in[21];
    const float* m2W  = (const float*)d_in[22];
    const float* m2b  = (const float*)d_in[23];

    float* out  = (float*)d_out;
    float* cons = out + (size_t)NT*DD;

    k_pre  <<<NT/16, 256>>>(x, g1, qW, qb, kdW, kdb, kuW, kub);
    k_ctx  <<<BB*HH*4, 256>>>();
    k_fused<<<NT/16, 256>>>(oW, ob, rot, tqs, s1W, s1b, s2W, s2b, x, g2, gateW, gateb);
    k_moe  <<<EE, 128>>>(expW);
    k_moe_b<<<NT/16, 256>>>(m1W, m1b, m2W, m2b, out, cons);
}

// round 5
// speedup vs baseline: 1.3600x; 1.1425x over previous
#include <cuda_runtime.h>
#include <math.h>

#define NT 2048      // B*T tokens
#define DD 128       // d_model
#define TT 512
#define BB 4
#define HH 8
#define EE 256
#define EPS 1e-6f
#define MAXB 4096    // bin capacity per expert (worst case)

// ---------------- scratch (device globals: allocation-free) ----------------
__device__ float g_q [NT*DD];
__device__ float g_k [NT*DD];
__device__ float g_v [NT*DD];
__device__ float g_ctxp [4*32*256];    // [part][bh][d*16+e]
__device__ float g_ksump[4*32*16];     // [part][bh][d]
__device__ float g_x2[NT*DD];
__device__ float g_h2[NT*DD];
__device__ float g_y [NT*256];         // [t][slot][128]
__device__ float g_ew[NT*2];
__device__ int   g_cnt[EE];
__device__ int   g_bin[EE*MAXB];       // packed t*2+slot

// ---------------- helpers ----------------
__device__ __forceinline__ float warp_sum(float v){
#pragma unroll
    for (int o = 16; o > 0; o >>= 1) v += __shfl_xor_sync(0xffffffffu, v, o);
    return v;
}
__device__ __forceinline__ float warp_max(float v){
#pragma unroll
    for (int o = 16; o > 0; o >>= 1) v = fmaxf(v, __shfl_xor_sync(0xffffffffu, v, o));
    return v;
}
__device__ __forceinline__ float elu1(float z){ return z > 0.f ? z + 1.f : expf(z); }
__device__ __forceinline__ float silu(float g){ return g / (1.f + expf(-g)); }

// split-K half matmul: acc[r] = sum_{i in [g*64,(g+1)*64)} aT[i][r] * W[i*128+o]
__device__ __forceinline__ void mm16h(const float* __restrict__ aT,
                                      const float* __restrict__ W,
                                      int o, int g, float acc[16]){
#pragma unroll
    for (int r = 0; r < 16; r++) acc[r] = 0.f;
    const float*  Wp = W + (size_t)(g*64)*128 + o;
    const float4* ap = (const float4*)(aT + (g*64)*16);
#pragma unroll 4
    for (int i = 0; i < 64; i++){
        float w = Wp[i*128];
        float4 a0 = ap[i*4+0], a1 = ap[i*4+1], a2 = ap[i*4+2], a3 = ap[i*4+3];
        acc[0]+=a0.x*w; acc[1]+=a0.y*w; acc[2]+=a0.z*w; acc[3]+=a0.w*w;
        acc[4]+=a1.x*w; acc[5]+=a1.y*w; acc[6]+=a1.z*w; acc[7]+=a1.w*w;
        acc[8]+=a2.x*w; acc[9]+=a2.y*w; acc[10]+=a2.z*w; acc[11]+=a2.w*w;
        acc[12]+=a3.x*w; acc[13]+=a3.y*w; acc[14]+=a3.z*w; acc[15]+=a3.w*w;
    }
}

__device__ __forceinline__ void mm16h_dual(const float* __restrict__ aT,
                                           const float* __restrict__ W1,
                                           const float* __restrict__ W2,
                                           int o, int g, float a1o[16], float a2o[16]){
#pragma unroll
    for (int r = 0; r < 16; r++){ a1o[r]=0.f; a2o[r]=0.f; }
    const float*  W1p = W1 + (size_t)(g*64)*128 + o;
    const float*  W2p = W2 + (size_t)(g*64)*128 + o;
    const float4* ap  = (const float4*)(aT + (g*64)*16);
#pragma unroll 2
    for (int i = 0; i < 64; i++){
        float w1 = W1p[i*128];
        float w2 = W2p[i*128];
        float4 a0 = ap[i*4+0], a1 = ap[i*4+1], a2 = ap[i*4+2], a3 = ap[i*4+3];
        a1o[0]+=a0.x*w1; a1o[1]+=a0.y*w1; a1o[2]+=a0.z*w1; a1o[3]+=a0.w*w1;
        a1o[4]+=a1.x*w1; a1o[5]+=a1.y*w1; a1o[6]+=a1.z*w1; a1o[7]+=a1.w*w1;
        a1o[8]+=a2.x*w1; a1o[9]+=a2.y*w1; a1o[10]+=a2.z*w1; a1o[11]+=a2.w*w1;
        a1o[12]+=a3.x*w1; a1o[13]+=a3.y*w1; a1o[14]+=a3.z*w1; a1o[15]+=a3.w*w1;
        a2o[0]+=a0.x*w2; a2o[1]+=a0.y*w2; a2o[2]+=a0.z*w2; a2o[3]+=a0.w*w2;
        a2o[4]+=a1.x*w2; a2o[5]+=a1.y*w2; a2o[6]+=a1.z*w2; a2o[7]+=a1.w*w2;
        a2o[8]+=a2.x*w2; a2o[9]+=a2.y*w2; a2o[10]+=a2.z*w2; a2o[11]+=a2.w*w2;
        a2o[12]+=a3.x*w2; a2o[13]+=a3.y*w2; a2o[14]+=a3.z*w2; a2o[15]+=a3.w*w2;
    }
}

// ---------------- K1: rmsnorm1 + q/kd/kv projections (fused, 256 thr split-K) ----------------
__global__ void k_pre(const float* __restrict__ x,   const float* __restrict__ g1,
                      const float* __restrict__ qW,  const float* __restrict__ qb,
                      const float* __restrict__ kdW, const float* __restrict__ kdb,
                      const float* __restrict__ kuW, const float* __restrict__ kub){
    __shared__ __align__(16) float aT [128*16];
    __shared__ __align__(16) float red[128*16];
    __shared__ __align__(16) float kdT[32*16];
    int tid = threadIdx.x;
    int c = tid & 127, g = tid >> 7;
    int w = tid >> 5,  l = tid & 31;
    int t0 = blockIdx.x*16;

    // zero MoE bin counters once (block 0)
    if (blockIdx.x == 0) g_cnt[tid & 255] = 0;

    // rmsnorm: warp w handles tokens w*2, w*2+1
#pragma unroll
    for (int tt = 0; tt < 2; tt++){
        int tok = w*2 + tt;
        const float* xr = x + (size_t)(t0+tok)*DD;
        float s = 0.f;
#pragma unroll
        for (int j = 0; j < 4; j++){ float v = xr[l+32*j]; s += v*v; }
        s = warp_sum(s);
        float rinv = rsqrtf(s*(1.f/128.f) + EPS);
#pragma unroll
        for (int j = 0; j < 4; j++){
            int i = l + 32*j;
            aT[i*16 + tok] = g1[i]*xr[i]*rinv;
        }
    }
    __syncthreads();

    // q = h1 @ qW + qb, elu+1   (split-K)
    {
        float acc[16];
        mm16h(aT, qW, c, g, acc);
        if (g){
#pragma unroll
            for (int r = 0; r < 16; r++) red[c*16+r] = acc[r];
        }
        __syncthreads();
        if (!g){
            float b = qb[c];
#pragma unroll
            for (int r = 0; r < 16; r++)
                g_q[(size_t)(t0+r)*DD + c] = elu1(acc[r] + red[c*16+r] + b);
        }
        __syncthreads();
    }

    // kd = h1 @ kdW + kdb  (32 outputs, split-K)
    {
        float acc[16];
#pragma unroll
        for (int r = 0; r < 16; r++) acc[r] = 0.f;
        if (c < 32){
            const float*  Wp = kdW + (size_t)(g*64)*32 + c;
            const float4* ap = (const float4*)(aT + (g*64)*16);
#pragma unroll 4
            for (int i = 0; i < 64; i++){
                float wv = Wp[i*32];
                float4 a0 = ap[i*4+0], a1 = ap[i*4+1], a2 = ap[i*4+2], a3 = ap[i*4+3];
                acc[0]+=a0.x*wv; acc[1]+=a0.y*wv; acc[2]+=a0.z*wv; acc[3]+=a0.w*wv;
                acc[4]+=a1.x*wv; acc[5]+=a1.y*wv; acc[6]+=a1.z*wv; acc[7]+=a1.w*wv;
                acc[8]+=a2.x*wv; acc[9]+=a2.y*wv; acc[10]+=a2.z*wv; acc[11]+=a2.w*wv;
                acc[12]+=a3.x*wv; acc[13]+=a3.y*wv; acc[14]+=a3.z*wv; acc[15]+=a3.w*wv;
            }
        }
        if (g && c < 32){
#pragma unroll
            for (int r = 0; r < 16; r++) red[c*16+r] = acc[r];
        }
        __syncthreads();
        if (!g && c < 32){
            float b = kdb[c];
#pragma unroll
            for (int r = 0; r < 16; r++) kdT[c*16+r] = acc[r] + red[c*16+r] + b;
        }
        __syncthreads();
    }

    // kv = kd @ kuW + kub : 256 outputs, one per thread, full K=32
    {
        int oo = tid;
        float acc[16];
#pragma unroll
        for (int r = 0; r < 16; r++) acc[r] = 0.f;
        const float*  Wp = kuW + oo;
        const float4* ap = (const float4*)kdT;
#pragma unroll 4
        for (int i = 0; i < 32; i++){
            float wv = Wp[i*256];
            float4 a0 = ap[i*4+0], a1 = ap[i*4+1], a2 = ap[i*4+2], a3 = ap[i*4+3];
            acc[0]+=a0.x*wv; acc[1]+=a0.y*wv; acc[2]+=a0.z*wv; acc[3]+=a0.w*wv;
            acc[4]+=a1.x*wv; acc[5]+=a1.y*wv; acc[6]+=a1.z*wv; acc[7]+=a1.w*wv;
            acc[8]+=a2.x*wv; acc[9]+=a2.y*wv; acc[10]+=a2.z*wv; acc[11]+=a2.w*wv;
            acc[12]+=a3.x*wv; acc[13]+=a3.y*wv; acc[14]+=a3.z*wv; acc[15]+=a3.w*wv;
        }
        int h = oo >> 5, p = oo & 31;
        float b = kub[oo];
#pragma unroll
        for (int r = 0; r < 16; r++){
            size_t t = t0 + r;
            float v = acc[r] + b;
            if (p < 16) g_k[t*DD + h*16 + p]        = elu1(v);
            else        g_v[t*DD + h*16 + (p-16)]   = v;
        }
    }
}

// ---------------- K2: partial context + ksum (4 T-partitions per (b,h)) ----------------
__global__ void k_ctx(){
    int bh = blockIdx.x >> 2, part = blockIdx.x & 3;
    int b = bh >> 3, h = bh & 7;
    int d = threadIdx.x >> 4, e = threadIdx.x & 15;
    const float* kp = g_k + ((size_t)(b*TT) + part*128)*DD + h*16 + d;
    const float* vp = g_v + ((size_t)(b*TT) + part*128)*DD + h*16 + e;
    float acc = 0.f, ks = 0.f;
#pragma unroll 8
    for (int t = 0; t < 128; t++){
        float kv_ = kp[t*DD];
        float vv  = vp[t*DD];
        acc += kv_ * vv;
        ks  += kv_;
    }
    g_ctxp[(part*32 + bh)*256 + d*16 + e] = acc;
    if (e == 0) g_ksump[(part*32 + bh)*16 + d] = ks;
}

// ---------------- top2 merge ----------------
__device__ __forceinline__ void top2_merge(float& v1, int& i1, float& v2, int& i2,
                                           float v, int i){
    if (v > v1 || (v == v1 && i < i1)){ v2 = v1; i2 = i1; v1 = v; i1 = i; }
    else if (v > v2 || (v == v2 && i < i2)){ v2 = v; i2 = i; }
}

// ---------------- K3: attn -> z -> oW -> rot -> TQ -> swiglu -> resid -> rms2 -> gate -> top2 -> bin ----------------
__global__ void k_fused(const float* __restrict__ oW,  const float* __restrict__ ob,
                        const float* __restrict__ rot, const float* __restrict__ tqs,
                        const float* __restrict__ s1W, const float* __restrict__ s1b,
                        const float* __restrict__ s2W, const float* __restrict__ s2b,
                        const float* __restrict__ x,   const float* __restrict__ g2,
                        const float* __restrict__ gateW, const float* __restrict__ gateb){
    __shared__ __align__(16) float u  [4096];  // ctx[2048]+q[2048], later gate logits [16][256]
    __shared__ __align__(16) float tA [2048];
    __shared__ __align__(16) float tB [2048];
    __shared__ __align__(16) float red[2048];
    __shared__ float zsh[128], ksum_sh[128], mags[16], rinvs[16];
    int tid = threadIdx.x;
    int c = tid & 127, g = tid >> 7;
    int w = tid >> 5,  l = tid & 31;
    int t0 = blockIdx.x*16, b = t0 >> 9;

    // load ctx (reduce 4 parts) and q tile
#pragma unroll
    for (int j = 0; j < 8; j++){
        int q = tid + 256*j;
        float s = 0.f;
#pragma unroll
        for (int p = 0; p < 4; p++) s += g_ctxp[p*8192 + b*2048 + q];
        u[q] = s;
        u[2048 + q] = g_q[(size_t)t0*DD + q];
    }
    if (!g){
        float s = 0.f;
#pragma unroll
        for (int p = 0; p < 4; p++) s += g_ksump[p*512 + b*128 + c];
        ksum_sh[c] = s;
    }
    __syncthreads();

    // z per (tok, head)
    if (!g){
        int tok = c >> 3, h = c & 7;
        float s = 0.f;
#pragma unroll
        for (int d = 0; d < 16; d++) s += u[2048 + tok*128 + h*16 + d]*ksum_sh[h*16 + d];
        zsh[c] = 1.f/(s + EPS);
    }
    __syncthreads();

    // attn: out[tok][h*16+e]; thread (c,g): col c, tokens g*8..g*8+7
    {
        int h = c >> 4, e = c & 15;
        float acc[8];
#pragma unroll
        for (int r = 0; r < 8; r++) acc[r] = 0.f;
#pragma unroll
        for (int d = 0; d < 16; d++){
            float cv = u[h*256 + d*16 + e];
#pragma unroll
            for (int r = 0; r < 8; r++) acc[r] += u[2048 + (g*8+r)*128 + h*16 + d]*cv;
        }
#pragma unroll
        for (int r = 0; r < 8; r++) tA[c*16 + g*8 + r] = acc[r]*zsh[(g*8+r)*8 + h];
    }
    __syncthreads();

    // oW: tA -> tB
    {
        float acc[16];
        mm16h(tA, oW, c, g, acc);
        if (g){
#pragma unroll
            for (int r = 0; r < 16; r++) red[c*16+r] = acc[r];
        }
        __syncthreads();
        if (!g){
            float bo = ob[c];
#pragma unroll
            for (int r = 0; r < 16; r++) tB[c*16+r] = acc[r] + red[c*16+r] + bo;
        }
        __syncthreads();
    }

    // rot: tB -> tA
    {
        float acc[16];
        mm16h(tB, rot, c, g, acc);
        if (g){
#pragma unroll
            for (int r = 0; r < 16; r++) red[c*16+r] = acc[r];
        }
        __syncthreads();
        if (!g){
#pragma unroll
            for (int r = 0; r < 16; r++) tA[c*16+r] = acc[r] + red[c*16+r];
        }
        __syncthreads();
    }

    // magnitudes per token
#pragma unroll
    for (int tt = 0; tt < 2; tt++){
        int tok = w*2 + tt;
        float s = 0.f;
#pragma unroll
        for (int j = 0; j < 4; j++){ float v = tA[(l+32*j)*16 + tok]; s += v*v; }
        s = warp_sum(s);
        if (l == 0) mags[tok] = sqrtf(s*(1.f/128.f) + EPS);
    }
    __syncthreads();

    // turbo quant: tA -> tB
#pragma unroll
    for (int j = 0; j < 8; j++){
        int q = tid + 256*j;
        int r = q & 15, o = q >> 4;
        float m  = mags[r];
        float ph = tA[q]/m;
        ph = fminf(fmaxf(ph, -1.f), 1.f);
        tB[q] = ph*m*tqs[o];
    }
    __syncthreads();

    // swiglu(s1,s2) + residual: tB -> x2 in tA + g_x2 (staged dual reduction)
    {
        float ag[16], au[16];
        mm16h_dual(tB, s1W, s2W, c, g, ag, au);
        if (g){
#pragma unroll
            for (int r = 0; r < 16; r++) red[c*16+r] = ag[r];
        }
        __syncthreads();
        if (!g){
#pragma unroll
            for (int r = 0; r < 16; r++) ag[r] += red[c*16+r];
        }
        __syncthreads();
        if (g){
#pragma unroll
            for (int r = 0; r < 16; r++) red[c*16+r] = au[r];
        }
        __syncthreads();
        if (!g){
            float b1 = s1b[c], b2 = s2b[c];
#pragma unroll
            for (int r = 0; r < 16; r++){
                float gg = ag[r] + b1;
                float uu = au[r] + red[c*16+r] + b2;
                float x2 = x[(size_t)(t0+r)*DD + c] + silu(gg)*uu;
                g_x2[(size_t)(t0+r)*DD + c] = x2;
                tA[c*16+r] = x2;
            }
        }
        __syncthreads();
    }

    // rmsnorm2
#pragma unroll
    for (int tt = 0; tt < 2; tt++){
        int tok = w*2 + tt;
        float s = 0.f;
#pragma unroll
        for (int j = 0; j < 4; j++){ float v = tA[(l+32*j)*16 + tok]; s += v*v; }
        s = warp_sum(s);
        if (l == 0) rinvs[tok] = rsqrtf(s*(1.f/128.f) + EPS);
    }
    __syncthreads();
    if (!g){
        float gg = g2[c];
#pragma unroll
        for (int r = 0; r < 16; r++){
            float h2 = gg * tA[c*16+r] * rinvs[r];
            g_h2[(size_t)(t0+r)*DD + c] = h2;
            tB[c*16+r] = h2;
        }
    }
    __syncthreads();

    // gate: 256 outputs, one per thread, full K
    {
        int oo = tid;
        float acc[16];
#pragma unroll
        for (int r = 0; r < 16; r++) acc[r] = 0.f;
        const float*  Wp = gateW + oo;
        const float4* ap = (const float4*)tB;
#pragma unroll 2
        for (int i = 0; i < 128; i++){
            float wv = Wp[i*256];
            float4 a0 = ap[i*4+0], a1 = ap[i*4+1], a2 = ap[i*4+2], a3 = ap[i*4+3];
            acc[0]+=a0.x*wv; acc[1]+=a0.y*wv; acc[2]+=a0.z*wv; acc[3]+=a0.w*wv;
            acc[4]+=a1.x*wv; acc[5]+=a1.y*wv; acc[6]+=a1.z*wv; acc[7]+=a1.w*wv;
            acc[8]+=a2.x*wv; acc[9]+=a2.y*wv; acc[10]+=a2.z*wv; acc[11]+=a2.w*wv;
            acc[12]+=a3.x*wv; acc[13]+=a3.y*wv; acc[14]+=a3.z*wv; acc[15]+=a3.w*wv;
        }
        float bb = gateb[oo];
#pragma unroll
        for (int r = 0; r < 16; r++) u[r*256 + oo] = acc[r] + bb;
    }
    __syncthreads();

    // softmax + top2 + binning: 8 warps, 2 tokens each
#pragma unroll
    for (int tt = 0; tt < 2; tt++){
        int tok = w*2 + tt;
        const float* row = u + tok*256;
        float mx = -3.4e38f;
#pragma unroll
        for (int j = 0; j < 8; j++) mx = fmaxf(mx, row[l + 32*j]);
        mx = warp_max(mx);
        float sum = 0.f;
        float v1 = -3.4e38f, v2 = -3.4e38f; int i1 = 0x7fffffff, i2 = 0x7fffffff;
#pragma unroll
        for (int j = 0; j < 8; j++){
            int idx = l + 32*j;
            float v = row[idx];
            sum += expf(v - mx);
            top2_merge(v1, i1, v2, i2, v, idx);
        }
        sum = warp_sum(sum);
#pragma unroll
        for (int off = 16; off > 0; off >>= 1){
            float ov1 = __shfl_xor_sync(0xffffffffu, v1, off);
            int   oi1 = __shfl_xor_sync(0xffffffffu, i1, off);
            float ov2 = __shfl_xor_sync(0xffffffffu, v2, off);
            int   oi2 = __shfl_xor_sync(0xffffffffu, i2, off);
            top2_merge(v1, i1, v2, i2, ov1, oi1);
            top2_merge(v1, i1, v2, i2, ov2, oi2);
        }
        if (l == 0){
            int t = t0 + tok;
            float p1 = expf(v1 - mx)/sum;
            float p2 = expf(v2 - mx)/sum;
            float den = p1 + p2 + EPS;
            g_ew[2*t]   = p1/den;
            g_ew[2*t+1] = p2/den;
            int s1 = atomicAdd(&g_cnt[i1], 1);
            g_bin[i1*MAXB + s1] = 2*t;
            int s2 = atomicAdd(&g_cnt[i2], 1);
            g_bin[i2*MAXB + s2] = 2*t + 1;
        }
    }
}

// ---------------- K4: binned expert matvecs (256 thr, split-K, high-MLP) ----------------
__global__ void k_moe(const float* __restrict__ expW){
    __shared__ __align__(16) float hs [16*128];   // [r][i]
    __shared__ __align__(16) float red[16*128];   // [r][o]
    __shared__ int toks[16];
    int e = blockIdx.x;
    int tid = threadIdx.x;
    int o = tid & 127, gk = tid >> 7;
    int n = g_cnt[e];
    const float* Wp = expW + (size_t)e*16384 + (size_t)(gk*64)*128 + o;
    for (int c0 = 0; c0 < n; c0 += 16){
        int m = min(16, n - c0);
        if (tid < 16) toks[tid] = g_bin[e*MAXB + c0 + ((tid < m) ? tid : 0)];
        __syncthreads();
        // stage h tile [r][i], fully coalesced
#pragma unroll
        for (int j = 0; j < 8; j++){
            int idx = tid + 256*j;
            int r = idx >> 7, i = idx & 127;
            hs[idx] = g_h2[(size_t)(toks[r] >> 1)*DD + i];
        }
        __syncthreads();
        // split-K matvec: thread (o,gk) accumulates over 64 rows
        float acc[16];
#pragma unroll
        for (int r = 0; r < 16; r++) acc[r] = 0.f;
#pragma unroll 4
        for (int i4 = 0; i4 < 16; i4++){
            float w0 = Wp[(i4*4+0)*128];
            float w1 = Wp[(i4*4+1)*128];
            float w2 = Wp[(i4*4+2)*128];
            float w3 = Wp[(i4*4+3)*128];
#pragma unroll
            for (int r = 0; r < 16; r++){
                float4 h4 = ((const float4*)(hs + r*128 + gk*64))[i4];
                acc[r] += h4.x*w0 + h4.y*w1 + h4.z*w2 + h4.w*w3;
            }
        }
        if (gk){
#pragma unroll
            for (int r = 0; r < 16; r++) red[r*128 + o] = acc[r];
        }
        __syncthreads();
        if (!gk){
            for (int r = 0; r < m; r++){
                int pk = toks[r];
                g_y[(size_t)(pk >> 1)*256 + (pk & 1)*128 + o] = acc[r] + red[r*128 + o];
            }
        }
        __syncthreads();
    }
}

// ---------------- K5: wavg -> swiglu(m1,m2) -> residual + consensus ----------------
__global__ void k_moe_b(const float* __restrict__ m1W, const float* __restrict__ m1b,
                        const float* __restrict__ m2W, const float* __restrict__ m2b,
                        float* __restrict__ out, float* __restrict__ cons){
    __shared__ __align__(16) float aT [2048];
    __shared__ __align__(16) float red[2048];
    __shared__ float ews[32];
    int tid = threadIdx.x;
    int c = tid & 127, g = tid >> 7;
    int w = tid >> 5,  l = tid & 31;
    int t0 = blockIdx.x*16;

    if (tid < 32) ews[tid] = g_ew[t0*2 + tid];
#pragma unroll
    for (int j = 0; j < 8; j++){
        int q = tid + 256*j;
        int r = q & 15, o = q >> 4;
        size_t t = t0 + r;
        aT[q] = g_ew[2*t]*g_y[t*256 + o] + g_ew[2*t+1]*g_y[t*256 + 128 + o];
    }
    __syncthreads();

    float ag[16], au[16];
    mm16h_dual(aT, m1W, m2W, c, g, ag, au);
    if (g){
#pragma unroll
        for (int r = 0; r < 16; r++) red[c*16+r] = ag[r];
    }
    __syncthreads();
    if (!g){
#pragma unroll
        for (int r = 0; r < 16; r++) ag[r] += red[c*16+r];
    }
    __syncthreads();
    if (g){
#pragma unroll
        for (int r = 0; r < 16; r++) red[c*16+r] = au[r];
    }
    __syncthreads();
    if (!g){
        float b1 = m1b[c], b2 = m2b[c];
#pragma unroll
        for (int r = 0; r < 16; r++){
            size_t t = t0 + r;
            float gg = ag[r] + b1;
            float uu = au[r] + red[c*16+r] + b2;
            float ws = silu(gg)*uu;
            out[t*DD + c] = g_x2[t*DD + c] + ws;
            float w1 = ews[2*r], w2 = ews[2*r+1];
            float y1 = g_y[t*256 + c];
            float y2 = g_y[t*256 + 128 + c];
            float d1 = y1 - ws, d2 = y2 - ws;
            red[c*16+r] = w1*d1*d1 + w2*d2*d2;   // reuse red as wvar tile
        }
    }
    __syncthreads();

#pragma unroll
    for (int tt = 0; tt < 2; tt++){
        int tok = w*2 + tt;
        float s = 0.f;
#pragma unroll
        for (int j = 0; j < 4; j++) s += red[(l+32*j)*16 + tok];
        s = warp_sum(s);
        if (l == 0) cons[t0 + tok] = expf(-s*(1.f/128.f));
    }
}

// ---------------- launch ----------------
extern "C" void kernel_launch(void* const* d_in, const int* in_sizes, int n_in,
                              void* d_out, int out_size){
    const float* x    = (const float*)d_in[0];
    const float* g1   = (const float*)d_in[1];
    const float* qW   = (const float*)d_in[2];
    const float* qb   = (const float*)d_in[3];
    const float* kdW  = (const float*)d_in[4];
    const float* kdb  = (const float*)d_in[5];
    const float* kuW  = (const float*)d_in[6];
    const float* kub  = (const float*)d_in[7];
    const float* oW   = (const float*)d_in[8];
    const float* ob   = (const float*)d_in[9];
    const float* rot  = (const float*)d_in[10];
    const float* tqs  = (const float*)d_in[11];
    const float* s1W  = (const float*)d_in[12];
    const float* s1b  = (const float*)d_in[13];
    const float* s2W  = (const float*)d_in[14];
    const float* s2b  = (const float*)d_in[15];
    const float* g2   = (const float*)d_in[16];
    const float* gateW= (const float*)d_in[17];
    const float* gateb= (const float*)d_in[18];
    const float* expW = (const float*)d_in[19];
    const float* m1W  = (const float*)d_in[20];
    const float* m1b  = (const float*)d_in[21];
    const float* m2W  = (const float*)d_in[22];
    const float* m2b  = (const float*)d_in[23];

    float* out  = (float*)d_out;
    float* cons = out + (size_t)NT*DD;

    k_pre  <<<NT/16, 256>>>(x, g1, qW, qb, kdW, kdb, kuW, kub);
    k_ctx  <<<BB*HH*4, 256>>>();
    k_fused<<<NT/16, 256>>>(oW, ob, rot, tqs, s1W, s1b, s2W, s2b, x, g2, gateW, gateb);
    k_moe  <<<EE, 256>>>(expW);
    k_moe_b<<<NT/16, 256>>>(m1W, m1b, m2W, m2b, out, cons);
}

// round 6
// speedup vs baseline: 1.8763x; 1.3796x over previous
#include <cuda_runtime.h>
#include <math.h>

#define NT 2048      // B*T tokens
#define DD 128       // d_model
#define TT 512
#define BB 4
#define HH 8
#define EE 256
#define EPS 1e-6f
#define MAXB 4096    // bin capacity per expert (worst case)

// ---------------- scratch (device globals: allocation-free) ----------------
__device__ float g_q [NT*DD];
__device__ float g_k [NT*DD];
__device__ float g_v [NT*DD];
__device__ float g_ctxp [4*32*256];    // [part][bh][d*16+e]
__device__ float g_ksump[4*32*16];     // [part][bh][d]
__device__ float g_x2[NT*DD];
__device__ float g_h2[NT*DD];
__device__ float g_y [NT*256];         // [t][slot][128]
__device__ float g_ew[NT*2];
__device__ int   g_cnt[EE];
__device__ int   g_bin[EE*MAXB];       // packed t*2+slot
__device__ int   g_items[1024];        // (e<<16)|chunk
__device__ int   g_nitems;

// ---------------- helpers ----------------
__device__ __forceinline__ float warp_sum(float v){
#pragma unroll
    for (int o = 16; o > 0; o >>= 1) v += __shfl_xor_sync(0xffffffffu, v, o);
    return v;
}
__device__ __forceinline__ float warp_max(float v){
#pragma unroll
    for (int o = 16; o > 0; o >>= 1) v = fmaxf(v, __shfl_xor_sync(0xffffffffu, v, o));
    return v;
}
__device__ __forceinline__ float elu1(float z){ return z > 0.f ? z + 1.f : expf(z); }
__device__ __forceinline__ float silu(float g){ return g / (1.f + expf(-g)); }

// split-K half matmul, 8-token tile: acc[r] = sum_{i in [g*64,(g+1)*64)} aT[i][r]*W[i*128+o]
__device__ __forceinline__ void mm8h(const float* __restrict__ aT,
                                     const float* __restrict__ W,
                                     int o, int g, float acc[8]){
#pragma unroll
    for (int r = 0; r < 8; r++) acc[r] = 0.f;
    const float*  Wp = W + (size_t)(g*64)*128 + o;
    const float4* ap = (const float4*)(aT + (g*64)*8);
#pragma unroll 4
    for (int i = 0; i < 64; i++){
        float w = Wp[i*128];
        float4 a0 = ap[i*2+0], a1 = ap[i*2+1];
        acc[0]+=a0.x*w; acc[1]+=a0.y*w; acc[2]+=a0.z*w; acc[3]+=a0.w*w;
        acc[4]+=a1.x*w; acc[5]+=a1.y*w; acc[6]+=a1.z*w; acc[7]+=a1.w*w;
    }
}

__device__ __forceinline__ void mm8h_dual(const float* __restrict__ aT,
                                          const float* __restrict__ W1,
                                          const float* __restrict__ W2,
                                          int o, int g, float a1o[8], float a2o[8]){
#pragma unroll
    for (int r = 0; r < 8; r++){ a1o[r]=0.f; a2o[r]=0.f; }
    const float*  W1p = W1 + (size_t)(g*64)*128 + o;
    const float*  W2p = W2 + (size_t)(g*64)*128 + o;
    const float4* ap  = (const float4*)(aT + (g*64)*8);
#pragma unroll 4
    for (int i = 0; i < 64; i++){
        float w1 = W1p[i*128];
        float w2 = W2p[i*128];
        float4 a0 = ap[i*2+0], a1 = ap[i*2+1];
        a1o[0]+=a0.x*w1; a1o[1]+=a0.y*w1; a1o[2]+=a0.z*w1; a1o[3]+=a0.w*w1;
        a1o[4]+=a1.x*w1; a1o[5]+=a1.y*w1; a1o[6]+=a1.z*w1; a1o[7]+=a1.w*w1;
        a2o[0]+=a0.x*w2; a2o[1]+=a0.y*w2; a2o[2]+=a0.z*w2; a2o[3]+=a0.w*w2;
        a2o[4]+=a1.x*w2; a2o[5]+=a1.y*w2; a2o[6]+=a1.z*w2; a2o[7]+=a1.w*w2;
    }
}

// ---------------- K1: rmsnorm1 + q/kd/kv projections (8-token tile) ----------------
__global__ void k_pre(const float* __restrict__ x,   const float* __restrict__ g1,
                      const float* __restrict__ qW,  const float* __restrict__ qb,
                      const float* __restrict__ kdW, const float* __restrict__ kdb,
                      const float* __restrict__ kuW, const float* __restrict__ kub){
    __shared__ __align__(16) float aT [128*8];
    __shared__ __align__(16) float red[128*8];
    __shared__ __align__(16) float kdT[32*8];
    int tid = threadIdx.x;
    int c = tid & 127, g = tid >> 7;
    int w = tid >> 5,  l = tid & 31;
    int t0 = blockIdx.x*8;

    if (blockIdx.x == 0) g_cnt[tid & 255] = 0;

    // rmsnorm: warp w handles token w
    {
        int tok = w;
        const float* xr = x + (size_t)(t0+tok)*DD;
        float s = 0.f;
#pragma unroll
        for (int j = 0; j < 4; j++){ float v = xr[l+32*j]; s += v*v; }
        s = warp_sum(s);
        float rinv = rsqrtf(s*(1.f/128.f) + EPS);
#pragma unroll
        for (int j = 0; j < 4; j++){
            int i = l + 32*j;
            aT[i*8 + tok] = g1[i]*xr[i]*rinv;
        }
    }
    __syncthreads();

    // q = h1 @ qW + qb, elu+1   (split-K)
    {
        float acc[8];
        mm8h(aT, qW, c, g, acc);
        if (g){
#pragma unroll
            for (int r = 0; r < 8; r++) red[c*8+r] = acc[r];
        }
        __syncthreads();
        if (!g){
            float b = qb[c];
#pragma unroll
            for (int r = 0; r < 8; r++)
                g_q[(size_t)(t0+r)*DD + c] = elu1(acc[r] + red[c*8+r] + b);
        }
        __syncthreads();
    }

    // kd = h1 @ kdW + kdb  (32 outputs, split-K)
    {
        float acc[8];
#pragma unroll
        for (int r = 0; r < 8; r++) acc[r] = 0.f;
        if (c < 32){
            const float*  Wp = kdW + (size_t)(g*64)*32 + c;
            const float4* ap = (const float4*)(aT + (g*64)*8);
#pragma unroll 4
            for (int i = 0; i < 64; i++){
                float wv = Wp[i*32];
                float4 a0 = ap[i*2+0], a1 = ap[i*2+1];
                acc[0]+=a0.x*wv; acc[1]+=a0.y*wv; acc[2]+=a0.z*wv; acc[3]+=a0.w*wv;
                acc[4]+=a1.x*wv; acc[5]+=a1.y*wv; acc[6]+=a1.z*wv; acc[7]+=a1.w*wv;
            }
        }
        if (g && c < 32){
#pragma unroll
            for (int r = 0; r < 8; r++) red[c*8+r] = acc[r];
        }
        __syncthreads();
        if (!g && c < 32){
            float b = kdb[c];
#pragma unroll
            for (int r = 0; r < 8; r++) kdT[c*8+r] = acc[r] + red[c*8+r] + b;
        }
        __syncthreads();
    }

    // kv = kd @ kuW + kub : 256 outputs, one per thread, full K=32
    {
        int oo = tid;
        float acc[8];
#pragma unroll
        for (int r = 0; r < 8; r++) acc[r] = 0.f;
        const float*  Wp = kuW + oo;
        const float4* ap = (const float4*)kdT;
#pragma unroll 4
        for (int i = 0; i < 32; i++){
            float wv = Wp[i*256];
            float4 a0 = ap[i*2+0], a1 = ap[i*2+1];
            acc[0]+=a0.x*wv; acc[1]+=a0.y*wv; acc[2]+=a0.z*wv; acc[3]+=a0.w*wv;
            acc[4]+=a1.x*wv; acc[5]+=a1.y*wv; acc[6]+=a1.z*wv; acc[7]+=a1.w*wv;
        }
        int h = oo >> 5, p = oo & 31;
        float b = kub[oo];
#pragma unroll
        for (int r = 0; r < 8; r++){
            size_t t = t0 + r;
            float v = acc[r] + b;
            if (p < 16) g_k[t*DD + h*16 + p]        = elu1(v);
            else        g_v[t*DD + h*16 + (p-16)]   = v;
        }
    }
}

// ---------------- K2: partial context + ksum (4 T-partitions per (b,h)) ----------------
__global__ void k_ctx(){
    int bh = blockIdx.x >> 2, part = blockIdx.x & 3;
    int b = bh >> 3, h = bh & 7;
    int d = threadIdx.x >> 4, e = threadIdx.x & 15;
    const float* kp = g_k + ((size_t)(b*TT) + part*128)*DD + h*16 + d;
    const float* vp = g_v + ((size_t)(b*TT) + part*128)*DD + h*16 + e;
    float acc = 0.f, ks = 0.f;
#pragma unroll 8
    for (int t = 0; t < 128; t++){
        float kv_ = kp[t*DD];
        float vv  = vp[t*DD];
        acc += kv_ * vv;
        ks  += kv_;
    }
    g_ctxp[(part*32 + bh)*256 + d*16 + e] = acc;
    if (e == 0) g_ksump[(part*32 + bh)*16 + d] = ks;
}

// ---------------- top2 merge ----------------
__device__ __forceinline__ void top2_merge(float& v1, int& i1, float& v2, int& i2,
                                           float v, int i){
    if (v > v1 || (v == v1 && i < i1)){ v2 = v1; i2 = i1; v1 = v; i1 = i; }
    else if (v > v2 || (v == v2 && i < i2)){ v2 = v; i2 = i; }
}

// ---------------- K3: fused mid-section (8-token tile) ----------------
__global__ void k_fused(const float* __restrict__ oW,  const float* __restrict__ ob,
                        const float* __restrict__ rot, const float* __restrict__ tqs,
                        const float* __restrict__ s1W, const float* __restrict__ s1b,
                        const float* __restrict__ s2W, const float* __restrict__ s2b,
                        const float* __restrict__ x,   const float* __restrict__ g2,
                        const float* __restrict__ gateW, const float* __restrict__ gateb){
    __shared__ __align__(16) float u  [3072];  // ctx[2048]+q[1024]; later gate logits [8][256]
    __shared__ __align__(16) float tA [1024];
    __shared__ __align__(16) float tB [1024];
    __shared__ __align__(16) float red[1024];
    __shared__ float zsh[64], ksum_sh[128], mags[8], rinvs[8];
    int tid = threadIdx.x;
    int c = tid & 127, g = tid >> 7;
    int w = tid >> 5,  l = tid & 31;
    int t0 = blockIdx.x*8, b = t0 >> 9;

    // load ctx (reduce 4 parts) and q tile
#pragma unroll
    for (int j = 0; j < 8; j++){
        int q = tid + 256*j;
        float s = 0.f;
#pragma unroll
        for (int p = 0; p < 4; p++) s += g_ctxp[p*8192 + b*2048 + q];
        u[q] = s;
    }
#pragma unroll
    for (int j = 0; j < 4; j++){
        int q = tid + 256*j;
        u[2048 + q] = g_q[(size_t)t0*DD + q];
    }
    if (!g){
        float s = 0.f;
#pragma unroll
        for (int p = 0; p < 4; p++) s += g_ksump[p*512 + b*128 + c];
        ksum_sh[c] = s;
    }
    __syncthreads();

    // z per (tok, head)
    if (tid < 64){
        int tok = tid >> 3, h = tid & 7;
        float s = 0.f;
#pragma unroll
        for (int d = 0; d < 16; d++) s += u[2048 + tok*128 + h*16 + d]*ksum_sh[h*16 + d];
        zsh[tid] = 1.f/(s + EPS);
    }
    __syncthreads();

    // attn: thread (c,g): col c, tokens g*4..g*4+3
    {
        int h = c >> 4, e = c & 15;
        float acc[4];
#pragma unroll
        for (int r = 0; r < 4; r++) acc[r] = 0.f;
#pragma unroll
        for (int d = 0; d < 16; d++){
            float cv = u[h*256 + d*16 + e];
#pragma unroll
            for (int r = 0; r < 4; r++) acc[r] += u[2048 + (g*4+r)*128 + h*16 + d]*cv;
        }
#pragma unroll
        for (int r = 0; r < 4; r++) tA[c*8 + g*4 + r] = acc[r]*zsh[(g*4+r)*8 + h];
    }
    __syncthreads();

    // oW: tA -> tB
    {
        float acc[8];
        mm8h(tA, oW, c, g, acc);
        if (g){
#pragma unroll
            for (int r = 0; r < 8; r++) red[c*8+r] = acc[r];
        }
        __syncthreads();
        if (!g){
            float bo = ob[c];
#pragma unroll
            for (int r = 0; r < 8; r++) tB[c*8+r] = acc[r] + red[c*8+r] + bo;
        }
        __syncthreads();
    }

    // rot: tB -> tA
    {
        float acc[8];
        mm8h(tB, rot, c, g, acc);
        if (g){
#pragma unroll
            for (int r = 0; r < 8; r++) red[c*8+r] = acc[r];
        }
        __syncthreads();
        if (!g){
#pragma unroll
            for (int r = 0; r < 8; r++) tA[c*8+r] = acc[r] + red[c*8+r];
        }
        __syncthreads();
    }

    // magnitudes per token (warp w -> token w)
    {
        float s = 0.f;
#pragma unroll
        for (int j = 0; j < 4; j++){ float v = tA[(l+32*j)*8 + w]; s += v*v; }
        s = warp_sum(s);
        if (l == 0) mags[w] = sqrtf(s*(1.f/128.f) + EPS);
    }
    __syncthreads();

    // turbo quant: tA -> tB
#pragma unroll
    for (int j = 0; j < 4; j++){
        int q = tid + 256*j;
        int r = q & 7, o = q >> 3;
        float m  = mags[r];
        float ph = tA[q]/m;
        ph = fminf(fmaxf(ph, -1.f), 1.f);
        tB[q] = ph*m*tqs[o];
    }
    __syncthreads();

    // swiglu(s1,s2) + residual -> x2 in tA + g_x2
    {
        float ag[8], au[8];
        mm8h_dual(tB, s1W, s2W, c, g, ag, au);
        if (g){
#pragma unroll
            for (int r = 0; r < 8; r++) red[c*8+r] = ag[r];
        }
        __syncthreads();
        if (!g){
#pragma unroll
            for (int r = 0; r < 8; r++) ag[r] += red[c*8+r];
        }
        __syncthreads();
        if (g){
#pragma unroll
            for (int r = 0; r < 8; r++) red[c*8+r] = au[r];
        }
        __syncthreads();
        if (!g){
            float b1 = s1b[c], b2 = s2b[c];
#pragma unroll
            for (int r = 0; r < 8; r++){
                float gg = ag[r] + b1;
                float uu = au[r] + red[c*8+r] + b2;
                float x2 = x[(size_t)(t0+r)*DD + c] + silu(gg)*uu;
                g_x2[(size_t)(t0+r)*DD + c] = x2;
                tA[c*8+r] = x2;
            }
        }
        __syncthreads();
    }

    // rmsnorm2 (warp w -> token w)
    {
        float s = 0.f;
#pragma unroll
        for (int j = 0; j < 4; j++){ float v = tA[(l+32*j)*8 + w]; s += v*v; }
        s = warp_sum(s);
        if (l == 0) rinvs[w] = rsqrtf(s*(1.f/128.f) + EPS);
    }
    __syncthreads();
    if (!g){
        float gg = g2[c];
#pragma unroll
        for (int r = 0; r < 8; r++){
            float h2 = gg * tA[c*8+r] * rinvs[r];
            g_h2[(size_t)(t0+r)*DD + c] = h2;
            tB[c*8+r] = h2;
        }
    }
    __syncthreads();

    // gate: 256 outputs, one per thread, full K=128
    {
        int oo = tid;
        float acc[8];
#pragma unroll
        for (int r = 0; r < 8; r++) acc[r] = 0.f;
        const float*  Wp = gateW + oo;
        const float4* ap = (const float4*)tB;
#pragma unroll 4
        for (int i = 0; i < 128; i++){
            float wv = Wp[i*256];
            float4 a0 = ap[i*2+0], a1 = ap[i*2+1];
            acc[0]+=a0.x*wv; acc[1]+=a0.y*wv; acc[2]+=a0.z*wv; acc[3]+=a0.w*wv;
            acc[4]+=a1.x*wv; acc[5]+=a1.y*wv; acc[6]+=a1.z*wv; acc[7]+=a1.w*wv;
        }
        float bb = gateb[oo];
#pragma unroll
        for (int r = 0; r < 8; r++) u[r*256 + oo] = acc[r] + bb;
    }
    __syncthreads();

    // softmax + top2 + binning: warp w -> token w
    {
        const float* row = u + w*256;
        float mx = -3.4e38f;
#pragma unroll
        for (int j = 0; j < 8; j++) mx = fmaxf(mx, row[l + 32*j]);
        mx = warp_max(mx);
        float sum = 0.f;
        float v1 = -3.4e38f, v2 = -3.4e38f; int i1 = 0x7fffffff, i2 = 0x7fffffff;
#pragma unroll
        for (int j = 0; j < 8; j++){
            int idx = l + 32*j;
            float v = row[idx];
            sum += expf(v - mx);
            top2_merge(v1, i1, v2, i2, v, idx);
        }
        sum = warp_sum(sum);
#pragma unroll
        for (int off = 16; off > 0; off >>= 1){
            float ov1 = __shfl_xor_sync(0xffffffffu, v1, off);
            int   oi1 = __shfl_xor_sync(0xffffffffu, i1, off);
            float ov2 = __shfl_xor_sync(0xffffffffu, v2, off);
            int   oi2 = __shfl_xor_sync(0xffffffffu, i2, off);
            top2_merge(v1, i1, v2, i2, ov1, oi1);
            top2_merge(v1, i1, v2, i2, ov2, oi2);
        }
        if (l == 0){
            int t = t0 + w;
            float p1 = expf(v1 - mx)/sum;
            float p2 = expf(v2 - mx)/sum;
            float den = p1 + p2 + EPS;
            g_ew[2*t]   = p1/den;
            g_ew[2*t+1] = p2/den;
            int s1 = atomicAdd(&g_cnt[i1], 1);
            g_bin[i1*MAXB + s1] = 2*t;
            int s2 = atomicAdd(&g_cnt[i2], 1);
            g_bin[i2*MAXB + s2] = 2*t + 1;
        }
    }
}

// ---------------- K3.5: build balanced work list of (expert, chunk) items ----------------
__global__ void k_sched(){
    __shared__ int warp_tot[8];
    int e = threadIdx.x;
    int l = e & 31, w = e >> 5;
    int n  = g_cnt[e];
    int ch = (n + 15) >> 4;
    int v = ch;
#pragma unroll
    for (int off = 1; off < 32; off <<= 1){
        int t = __shfl_up_sync(0xffffffffu, v, off);
        if (l >= off) v += t;
    }
    if (l == 31) warp_tot[w] = v;
    __syncthreads();
    int base = 0;
    for (int i = 0; i < w; i++) base += warp_tot[i];
    int excl = base + v - ch;
    for (int c = 0; c < ch; c++) g_items[excl + c] = (e << 16) | c;
    if (e == 255) g_nitems = excl + ch;
}

// ---------------- K4: work-list expert matvecs (grid-stride over items) ----------------
__global__ void k_moe(const float* __restrict__ expW){
    __shared__ __align__(16) float hs [16*128];   // [r][i]
    __shared__ __align__(16) float red[16*128];   // [r][o]
    __shared__ int toks[16];
    int tid = threadIdx.x;
    int o = tid & 127, gk = tid >> 7;
    int n_items = g_nitems;
    for (int it = blockIdx.x; it < n_items; it += gridDim.x){
        int item = g_items[it];
        int e = item >> 16;
        int c0 = (item & 0xffff) << 4;
        int n = g_cnt[e];
        int m = min(16, n - c0);
        if (tid < 16) toks[tid] = g_bin[e*MAXB + c0 + ((tid < m) ? tid : 0)];
        __syncthreads();
#pragma unroll
        for (int j = 0; j < 8; j++){
            int idx = tid + 256*j;
            int r = idx >> 7, i = idx & 127;
            hs[idx] = g_h2[(size_t)(toks[r] >> 1)*DD + i];
        }
        __syncthreads();
        const float* Wp = expW + (size_t)e*16384 + (size_t)(gk*64)*128 + o;
        float acc[16];
#pragma unroll
        for (int r = 0; r < 16; r++) acc[r] = 0.f;
#pragma unroll 4
        for (int i4 = 0; i4 < 16; i4++){
            float w0 = Wp[(i4*4+0)*128];
            float w1 = Wp[(i4*4+1)*128];
            float w2 = Wp[(i4*4+2)*128];
            float w3 = Wp[(i4*4+3)*128];
#pragma unroll
            for (int r = 0; r < 16; r++){
                float4 h4 = ((const float4*)(hs + r*128 + gk*64))[i4];
                acc[r] += h4.x*w0 + h4.y*w1 + h4.z*w2 + h4.w*w3;
            }
        }
        if (gk){
#pragma unroll
            for (int r = 0; r < 16; r++) red[r*128 + o] = acc[r];
        }
        __syncthreads();
        if (!gk){
            for (int r = 0; r < m; r++){
                int pk = toks[r];
                g_y[(size_t)(pk >> 1)*256 + (pk & 1)*128 + o] = acc[r] + red[r*128 + o];
            }
        }
        __syncthreads();
    }
}

// ---------------- K5: wavg -> swiglu(m1,m2) -> residual + consensus (8-token tile) ----------------
__global__ void k_moe_b(const float* __restrict__ m1W, const float* __restrict__ m1b,
                        const float* __restrict__ m2W, const float* __restrict__ m2b,
                        float* __restrict__ out, float* __restrict__ cons){
    __shared__ __align__(16) float aT [1024];
    __shared__ __align__(16) float red[1024];
    __shared__ float ews[16];
    int tid = threadIdx.x;
    int c = tid & 127, g = tid >> 7;
    int w = tid >> 5,  l = tid & 31;
    int t0 = blockIdx.x*8;

    if (tid < 16) ews[tid] = g_ew[t0*2 + tid];
#pragma unroll
    for (int j = 0; j < 4; j++){
        int q = tid + 256*j;
        int r = q & 7, o = q >> 3;
        size_t t = t0 + r;
        aT[q] = g_ew[2*t]*g_y[t*256 + o] + g_ew[2*t+1]*g_y[t*256 + 128 + o];
    }
    __syncthreads();

    float ag[8], au[8];
    mm8h_dual(aT, m1W, m2W, c, g, ag, au);
    if (g){
#pragma unroll
        for (int r = 0; r < 8; r++) red[c*8+r] = ag[r];
    }
    __syncthreads();
    if (!g){
#pragma unroll
        for (int r = 0; r < 8; r++) ag[r] += red[c*8+r];
    }
    __syncthreads();
    if (g){
#pragma unroll
        for (int r = 0; r < 8; r++) red[c*8+r] = au[r];
    }
    __syncthreads();
    if (!g){
        float b1 = m1b[c], b2 = m2b[c];
#pragma unroll
        for (int r = 0; r < 8; r++){
            size_t t = t0 + r;
            float gg = ag[r] + b1;
            float uu = au[r] + red[c*8+r] + b2;
            float ws = silu(gg)*uu;
            out[t*DD + c] = g_x2[t*DD + c] + ws;
            float w1 = ews[2*r], w2 = ews[2*r+1];
            float y1 = g_y[t*256 + c];
            float y2 = g_y[t*256 + 128 + c];
            float d1 = y1 - ws, d2 = y2 - ws;
            red[c*8+r] = w1*d1*d1 + w2*d2*d2;   // reuse red as wvar tile
        }
    }
    __syncthreads();

    // consensus: warp w -> token w
    {
        float s = 0.f;
#pragma unroll
        for (int j = 0; j < 4; j++) s += red[(l+32*j)*8 + w];
        s = warp_sum(s);
        if (l == 0) cons[t0 + w] = expf(-s*(1.f/128.f));
    }
}

// ---------------- launch ----------------
extern "C" void kernel_launch(void* const* d_in, const int* in_sizes, int n_in,
                              void* d_out, int out_size){
    const float* x    = (const float*)d_in[0];
    const float* g1   = (const float*)d_in[1];
    const float* qW   = (const float*)d_in[2];
    const float* qb   = (const float*)d_in[3];
    const float* kdW  = (const float*)d_in[4];
    const float* kdb  = (const float*)d_in[5];
    const float* kuW  = (const float*)d_in[6];
    const float* kub  = (const float*)d_in[7];
    const float* oW   = (const float*)d_in[8];
    const float* ob   = (const float*)d_in[9];
    const float* rot  = (const float*)d_in[10];
    const float* tqs  = (const float*)d_in[11];
    const float* s1W  = (const float*)d_in[12];
    const float* s1b  = (const float*)d_in[13];
    const float* s2W  = (const float*)d_in[14];
    const float* s2b  = (const float*)d_in[15];
    const float* g2   = (const float*)d_in[16];
    const float* gateW= (const float*)d_in[17];
    const float* gateb= (const float*)d_in[18];
    const float* expW = (const float*)d_in[19];
    const float* m1W  = (const float*)d_in[20];
    const float* m1b  = (const float*)d_in[21];
    const float* m2W  = (const float*)d_in[22];
    const float* m2b  = (const float*)d_in[23];

    float* out  = (float*)d_out;
    float* cons = out + (size_t)NT*DD;

    k_pre  <<<NT/8, 256>>>(x, g1, qW, qb, kdW, kdb, kuW, kub);
    k_ctx  <<<BB*HH*4, 256>>>();
    k_fused<<<NT/8, 256>>>(oW, ob, rot, tqs, s1W, s1b, s2W, s2b, x, g2, gateW, gateb);
    k_sched<<<1, 256>>>();
    k_moe  <<<512, 256>>>(expW);
    k_moe_b<<<NT/8, 256>>>(m1W, m1b, m2W, m2b, out, cons);
}

// round 7
// speedup vs baseline: 2.0113x; 1.0719x over previous
#include <cuda_runtime.h>
#include <math.h>

#define NT 2048      // B*T tokens
#define DD 128       // d_model
#define TT 512
#define BB 4
#define HH 8
#define EE 256
#define EPS 1e-6f
#define MAXB 4096    // bin capacity per expert (worst case)

// ---------------- scratch (device globals: allocation-free) ----------------
__device__ float g_q [NT*DD];
__device__ float g_k [NT*DD];
__device__ float g_v [NT*DD];
__device__ float g_ctxp [4*32*256];    // [part][bh][d*16+e]
__device__ float g_ksump[4*32*16];     // [part][bh][d]
__device__ float g_x2[NT*DD];
__device__ float g_h2[NT*DD];
__device__ float g_y [NT*256];         // [t][slot][128]
__device__ float g_ew[NT*2];
__device__ int   g_cnt[EE];
__device__ int   g_bin[EE*MAXB];       // packed t*2+slot
__device__ int   g_items[1024];        // (e<<16)|chunk
__device__ int   g_nitems;
__device__ int   g_done = 0;

// ---------------- helpers ----------------
__device__ __forceinline__ float warp_sum(float v){
#pragma unroll
    for (int o = 16; o > 0; o >>= 1) v += __shfl_xor_sync(0xffffffffu, v, o);
    return v;
}
__device__ __forceinline__ float warp_max(float v){
#pragma unroll
    for (int o = 16; o > 0; o >>= 1) v = fmaxf(v, __shfl_xor_sync(0xffffffffu, v, o));
    return v;
}
__device__ __forceinline__ float elu1(float z){ return z > 0.f ? z + 1.f : expf(z); }
__device__ __forceinline__ float silu(float g){ return g / (1.f + expf(-g)); }

// split-K half matmul, 8-token tile: acc[r] = sum_{i in [g*64,(g+1)*64)} aT[i][r]*W[i*128+o]
__device__ __forceinline__ void mm8h(const float* __restrict__ aT,
                                     const float* __restrict__ W,
                                     int o, int g, float acc[8]){
#pragma unroll
    for (int r = 0; r < 8; r++) acc[r] = 0.f;
    const float*  Wp = W + (size_t)(g*64)*128 + o;
    const float4* ap = (const float4*)(aT + (g*64)*8);
#pragma unroll 8
    for (int i = 0; i < 64; i++){
        float w = Wp[i*128];
        float4 a0 = ap[i*2+0], a1 = ap[i*2+1];
        acc[0]+=a0.x*w; acc[1]+=a0.y*w; acc[2]+=a0.z*w; acc[3]+=a0.w*w;
        acc[4]+=a1.x*w; acc[5]+=a1.y*w; acc[6]+=a1.z*w; acc[7]+=a1.w*w;
    }
}

__device__ __forceinline__ void mm8h_dual(const float* __restrict__ aT,
                                          const float* __restrict__ W1,
                                          const float* __restrict__ W2,
                                          int o, int g, float a1o[8], float a2o[8]){
#pragma unroll
    for (int r = 0; r < 8; r++){ a1o[r]=0.f; a2o[r]=0.f; }
    const float*  W1p = W1 + (size_t)(g*64)*128 + o;
    const float*  W2p = W2 + (size_t)(g*64)*128 + o;
    const float4* ap  = (const float4*)(aT + (g*64)*8);
#pragma unroll 8
    for (int i = 0; i < 64; i++){
        float w1 = W1p[i*128];
        float w2 = W2p[i*128];
        float4 a0 = ap[i*2+0], a1 = ap[i*2+1];
        a1o[0]+=a0.x*w1; a1o[1]+=a0.y*w1; a1o[2]+=a0.z*w1; a1o[3]+=a0.w*w1;
        a1o[4]+=a1.x*w1; a1o[5]+=a1.y*w1; a1o[6]+=a1.z*w1; a1o[7]+=a1.w*w1;
        a2o[0]+=a0.x*w2; a2o[1]+=a0.y*w2; a2o[2]+=a0.z*w2; a2o[3]+=a0.w*w2;
        a2o[4]+=a1.x*w2; a2o[5]+=a1.y*w2; a2o[6]+=a1.z*w2; a2o[7]+=a1.w*w2;
    }
}

// ---------------- K1: rmsnorm1 + q/kd/kv projections (8-token tile) ----------------
__global__ void k_pre(const float* __restrict__ x,   const float* __restrict__ g1,
                      const float* __restrict__ qW,  const float* __restrict__ qb,
                      const float* __restrict__ kdW, const float* __restrict__ kdb,
                      const float* __restrict__ kuW, const float* __restrict__ kub){
    __shared__ __align__(16) float aT [128*8];
    __shared__ __align__(16) float red[128*8];
    __shared__ __align__(16) float kdT[32*8];
    int tid = threadIdx.x;
    int c = tid & 127, g = tid >> 7;
    int w = tid >> 5,  l = tid & 31;
    int t0 = blockIdx.x*8;

    if (blockIdx.x == 0) g_cnt[tid & 255] = 0;

    // rmsnorm: warp w handles token w
    {
        int tok = w;
        const float* xr = x + (size_t)(t0+tok)*DD;
        float s = 0.f;
#pragma unroll
        for (int j = 0; j < 4; j++){ float v = xr[l+32*j]; s += v*v; }
        s = warp_sum(s);
        float rinv = rsqrtf(s*(1.f/128.f) + EPS);
#pragma unroll
        for (int j = 0; j < 4; j++){
            int i = l + 32*j;
            aT[i*8 + tok] = g1[i]*xr[i]*rinv;
        }
    }
    __syncthreads();

    // q = h1 @ qW + qb, elu+1   (split-K)
    {
        float acc[8];
        mm8h(aT, qW, c, g, acc);
        if (g){
#pragma unroll
            for (int r = 0; r < 8; r++) red[c*8+r] = acc[r];
        }
        __syncthreads();
        if (!g){
            float b = qb[c];
#pragma unroll
            for (int r = 0; r < 8; r++)
                g_q[(size_t)(t0+r)*DD + c] = elu1(acc[r] + red[c*8+r] + b);
        }
        __syncthreads();
    }

    // kd = h1 @ kdW + kdb  (32 outputs, split-K)
    {
        float acc[8];
#pragma unroll
        for (int r = 0; r < 8; r++) acc[r] = 0.f;
        if (c < 32){
            const float*  Wp = kdW + (size_t)(g*64)*32 + c;
            const float4* ap = (const float4*)(aT + (g*64)*8);
#pragma unroll 8
            for (int i = 0; i < 64; i++){
                float wv = Wp[i*32];
                float4 a0 = ap[i*2+0], a1 = ap[i*2+1];
                acc[0]+=a0.x*wv; acc[1]+=a0.y*wv; acc[2]+=a0.z*wv; acc[3]+=a0.w*wv;
                acc[4]+=a1.x*wv; acc[5]+=a1.y*wv; acc[6]+=a1.z*wv; acc[7]+=a1.w*wv;
            }
        }
        if (g && c < 32){
#pragma unroll
            for (int r = 0; r < 8; r++) red[c*8+r] = acc[r];
        }
        __syncthreads();
        if (!g && c < 32){
            float b = kdb[c];
#pragma unroll
            for (int r = 0; r < 8; r++) kdT[c*8+r] = acc[r] + red[c*8+r] + b;
        }
        __syncthreads();
    }

    // kv = kd @ kuW + kub : 256 outputs, one per thread, full K=32
    {
        int oo = tid;
        float acc[8];
#pragma unroll
        for (int r = 0; r < 8; r++) acc[r] = 0.f;
        const float*  Wp = kuW + oo;
        const float4* ap = (const float4*)kdT;
#pragma unroll 8
        for (int i = 0; i < 32; i++){
            float wv = Wp[i*256];
            float4 a0 = ap[i*2+0], a1 = ap[i*2+1];
            acc[0]+=a0.x*wv; acc[1]+=a0.y*wv; acc[2]+=a0.z*wv; acc[3]+=a0.w*wv;
            acc[4]+=a1.x*wv; acc[5]+=a1.y*wv; acc[6]+=a1.z*wv; acc[7]+=a1.w*wv;
        }
        int h = oo >> 5, p = oo & 31;
        float b = kub[oo];
#pragma unroll
        for (int r = 0; r < 8; r++){
            size_t t = t0 + r;
            float v = acc[r] + b;
            if (p < 16) g_k[t*DD + h*16 + p]        = elu1(v);
            else        g_v[t*DD + h*16 + (p-16)]   = v;
        }
    }
}

// ---------------- K2: partial context + ksum (4 T-partitions per (b,h)) ----------------
__global__ void k_ctx(){
    int bh = blockIdx.x >> 2, part = blockIdx.x & 3;
    int b = bh >> 3, h = bh & 7;
    int d = threadIdx.x >> 4, e = threadIdx.x & 15;
    const float* kp = g_k + ((size_t)(b*TT) + part*128)*DD + h*16 + d;
    const float* vp = g_v + ((size_t)(b*TT) + part*128)*DD + h*16 + e;
    float acc = 0.f, ks = 0.f;
#pragma unroll 8
    for (int t = 0; t < 128; t++){
        float kv_ = kp[t*DD];
        float vv  = vp[t*DD];
        acc += kv_ * vv;
        ks  += kv_;
    }
    g_ctxp[(part*32 + bh)*256 + d*16 + e] = acc;
    if (e == 0) g_ksump[(part*32 + bh)*16 + d] = ks;
}

// ---------------- top2 merge ----------------
__device__ __forceinline__ void top2_merge(float& v1, int& i1, float& v2, int& i2,
                                           float v, int i){
    if (v > v1 || (v == v1 && i < i1)){ v2 = v1; i2 = i1; v1 = v; i1 = i; }
    else if (v > v2 || (v == v2 && i < i2)){ v2 = v; i2 = i; }
}

// ---------------- K3: fused mid-section (8-token tile) + inline scheduler in last block ----------------
__global__ void k_fused(const float* __restrict__ oW,  const float* __restrict__ ob,
                        const float* __restrict__ rot, const float* __restrict__ tqs,
                        const float* __restrict__ s1W, const float* __restrict__ s1b,
                        const float* __restrict__ s2W, const float* __restrict__ s2b,
                        const float* __restrict__ x,   const float* __restrict__ g2,
                        const float* __restrict__ gateW, const float* __restrict__ gateb){
    __shared__ __align__(16) float u  [3072];  // ctx[2048]+q[1024]; later gate logits [8][256]
    __shared__ __align__(16) float tA [1024];
    __shared__ __align__(16) float tB [1024];
    __shared__ __align__(16) float red[1024];
    __shared__ float zsh[64], ksum_sh[128], mags[8], rinvs[8];
    __shared__ int   last_sh;
    __shared__ int   warp_tot[8];
    int tid = threadIdx.x;
    int c = tid & 127, g = tid >> 7;
    int w = tid >> 5,  l = tid & 31;
    int t0 = blockIdx.x*8, b = t0 >> 9;

    // load ctx (reduce 4 parts) and q tile
#pragma unroll
    for (int j = 0; j < 8; j++){
        int q = tid + 256*j;
        float s = 0.f;
#pragma unroll
        for (int p = 0; p < 4; p++) s += g_ctxp[p*8192 + b*2048 + q];
        u[q] = s;
    }
#pragma unroll
    for (int j = 0; j < 4; j++){
        int q = tid + 256*j;
        u[2048 + q] = g_q[(size_t)t0*DD + q];
    }
    if (!g){
        float s = 0.f;
#pragma unroll
        for (int p = 0; p < 4; p++) s += g_ksump[p*512 + b*128 + c];
        ksum_sh[c] = s;
    }
    __syncthreads();

    // z per (tok, head)
    if (tid < 64){
        int tok = tid >> 3, h = tid & 7;
        float s = 0.f;
#pragma unroll
        for (int d = 0; d < 16; d++) s += u[2048 + tok*128 + h*16 + d]*ksum_sh[h*16 + d];
        zsh[tid] = 1.f/(s + EPS);
    }
    __syncthreads();

    // attn: thread (c,g): col c, tokens g*4..g*4+3
    {
        int h = c >> 4, e = c & 15;
        float acc[4];
#pragma unroll
        for (int r = 0; r < 4; r++) acc[r] = 0.f;
#pragma unroll
        for (int d = 0; d < 16; d++){
            float cv = u[h*256 + d*16 + e];
#pragma unroll
            for (int r = 0; r < 4; r++) acc[r] += u[2048 + (g*4+r)*128 + h*16 + d]*cv;
        }
#pragma unroll
        for (int r = 0; r < 4; r++) tA[c*8 + g*4 + r] = acc[r]*zsh[(g*4+r)*8 + h];
    }
    __syncthreads();

    // oW: tA -> tB
    {
        float acc[8];
        mm8h(tA, oW, c, g, acc);
        if (g){
#pragma unroll
            for (int r = 0; r < 8; r++) red[c*8+r] = acc[r];
        }
        __syncthreads();
        if (!g){
            float bo = ob[c];
#pragma unroll
            for (int r = 0; r < 8; r++) tB[c*8+r] = acc[r] + red[c*8+r] + bo;
        }
        __syncthreads();
    }

    // rot: tB -> tA
    {
        float acc[8];
        mm8h(tB, rot, c, g, acc);
        if (g){
#pragma unroll
            for (int r = 0; r < 8; r++) red[c*8+r] = acc[r];
        }
        __syncthreads();
        if (!g){
#pragma unroll
            for (int r = 0; r < 8; r++) tA[c*8+r] = acc[r] + red[c*8+r];
        }
        __syncthreads();
    }

    // magnitudes per token (warp w -> token w)
    {
        float s = 0.f;
#pragma unroll
        for (int j = 0; j < 4; j++){ float v = tA[(l+32*j)*8 + w]; s += v*v; }
        s = warp_sum(s);
        if (l == 0) mags[w] = sqrtf(s*(1.f/128.f) + EPS);
    }
    __syncthreads();

    // turbo quant: tA -> tB
#pragma unroll
    for (int j = 0; j < 4; j++){
        int q = tid + 256*j;
        int r = q & 7, o = q >> 3;
        float m  = mags[r];
        float ph = tA[q]/m;
        ph = fminf(fmaxf(ph, -1.f), 1.f);
        tB[q] = ph*m*tqs[o];
    }
    __syncthreads();

    // swiglu(s1,s2) + residual -> x2 in tA + g_x2
    {
        float ag[8], au[8];
        mm8h_dual(tB, s1W, s2W, c, g, ag, au);
        if (g){
#pragma unroll
            for (int r = 0; r < 8; r++) red[c*8+r] = ag[r];
        }
        __syncthreads();
        if (!g){
#pragma unroll
            for (int r = 0; r < 8; r++) ag[r] += red[c*8+r];
        }
        __syncthreads();
        if (g){
#pragma unroll
            for (int r = 0; r < 8; r++) red[c*8+r] = au[r];
        }
        __syncthreads();
        if (!g){
            float b1 = s1b[c], b2 = s2b[c];
#pragma unroll
            for (int r = 0; r < 8; r++){
                float gg = ag[r] + b1;
                float uu = au[r] + red[c*8+r] + b2;
                float x2 = x[(size_t)(t0+r)*DD + c] + silu(gg)*uu;
                g_x2[(size_t)(t0+r)*DD + c] = x2;
                tA[c*8+r] = x2;
            }
        }
        __syncthreads();
    }

    // rmsnorm2 (warp w -> token w)
    {
        float s = 0.f;
#pragma unroll
        for (int j = 0; j < 4; j++){ float v = tA[(l+32*j)*8 + w]; s += v*v; }
        s = warp_sum(s);
        if (l == 0) rinvs[w] = rsqrtf(s*(1.f/128.f) + EPS);
    }
    __syncthreads();
    if (!g){
        float gg = g2[c];
#pragma unroll
        for (int r = 0; r < 8; r++){
            float h2 = gg * tA[c*8+r] * rinvs[r];
            g_h2[(size_t)(t0+r)*DD + c] = h2;
            tB[c*8+r] = h2;
        }
    }
    __syncthreads();

    // gate: 256 outputs, one per thread, full K=128
    {
        int oo = tid;
        float acc[8];
#pragma unroll
        for (int r = 0; r < 8; r++) acc[r] = 0.f;
        const float*  Wp = gateW + oo;
        const float4* ap = (const float4*)tB;
#pragma unroll 8
        for (int i = 0; i < 128; i++){
            float wv = Wp[i*256];
            float4 a0 = ap[i*2+0], a1 = ap[i*2+1];
            acc[0]+=a0.x*wv; acc[1]+=a0.y*wv; acc[2]+=a0.z*wv; acc[3]+=a0.w*wv;
            acc[4]+=a1.x*wv; acc[5]+=a1.y*wv; acc[6]+=a1.z*wv; acc[7]+=a1.w*wv;
        }
        float bb = gateb[oo];
#pragma unroll
        for (int r = 0; r < 8; r++) u[r*256 + oo] = acc[r] + bb;
    }
    __syncthreads();

    // softmax + top2 + binning: warp w -> token w
    {
        const float* row = u + w*256;
        float mx = -3.4e38f;
#pragma unroll
        for (int j = 0; j < 8; j++) mx = fmaxf(mx, row[l + 32*j]);
        mx = warp_max(mx);
        float sum = 0.f;
        float v1 = -3.4e38f, v2 = -3.4e38f; int i1 = 0x7fffffff, i2 = 0x7fffffff;
#pragma unroll
        for (int j = 0; j < 8; j++){
            int idx = l + 32*j;
            float v = row[idx];
            sum += expf(v - mx);
            top2_merge(v1, i1, v2, i2, v, idx);
        }
        sum = warp_sum(sum);
#pragma unroll
        for (int off = 16; off > 0; off >>= 1){
            float ov1 = __shfl_xor_sync(0xffffffffu, v1, off);
            int   oi1 = __shfl_xor_sync(0xffffffffu, i1, off);
            float ov2 = __shfl_xor_sync(0xffffffffu, v2, off);
            int   oi2 = __shfl_xor_sync(0xffffffffu, i2, off);
            top2_merge(v1, i1, v2, i2, ov1, oi1);
            top2_merge(v1, i1, v2, i2, ov2, oi2);
        }
        if (l == 0){
            int t = t0 + w;
            float p1 = expf(v1 - mx)/sum;
            float p2 = expf(v2 - mx)/sum;
            float den = p1 + p2 + EPS;
            g_ew[2*t]   = p1/den;
            g_ew[2*t+1] = p2/den;
            int s1 = atomicAdd(&g_cnt[i1], 1);
            g_bin[i1*MAXB + s1] = 2*t;
            int s2 = atomicAdd(&g_cnt[i2], 1);
            g_bin[i2*MAXB + s2] = 2*t + 1;
        }
    }

    // ---- inline scheduler: the last block to finish builds the work list ----
    __syncthreads();
    if (tid == 0){
        __threadfence();
        int d = atomicAdd(&g_done, 1);
        last_sh = (d == (int)gridDim.x - 1);
    }
    __syncthreads();
    if (last_sh){
        int e = tid;               // 256 threads -> 256 experts
        int n  = g_cnt[e];
        int ch = (n + 15) >> 4;
        int v = ch;
#pragma unroll
        for (int off = 1; off < 32; off <<= 1){
            int t = __shfl_up_sync(0xffffffffu, v, off);
            if (l >= off) v += t;
        }
        if (l == 31) warp_tot[w] = v;
        __syncthreads();
        int base = 0;
        for (int i = 0; i < w; i++) base += warp_tot[i];
        int excl = base + v - ch;
        for (int cc = 0; cc < ch; cc++) g_items[excl + cc] = (e << 16) | cc;
        if (e == 255){ g_nitems = excl + ch; g_done = 0; }
    }
}

// ---------------- K4: work-list expert matvecs (grid-stride over items) ----------------
__global__ void k_moe(const float* __restrict__ expW){
    __shared__ __align__(16) float hs [16*128];   // [r][i]
    __shared__ __align__(16) float red[16*128];   // [r][o]
    __shared__ int toks[16];
    int tid = threadIdx.x;
    int o = tid & 127, gk = tid >> 7;
    int n_items = g_nitems;
    for (int it = blockIdx.x; it < n_items; it += gridDim.x){
        int item = g_items[it];
        int e = item >> 16;
        int c0 = (item & 0xffff) << 4;
        int n = g_cnt[e];
        int m = min(16, n - c0);
        if (tid < 16) toks[tid] = g_bin[e*MAXB + c0 + ((tid < m) ? tid : 0)];
        __syncthreads();
#pragma unroll
        for (int j = 0; j < 8; j++){
            int idx = tid + 256*j;
            int r = idx >> 7, i = idx & 127;
            hs[idx] = g_h2[(size_t)(toks[r] >> 1)*DD + i];
        }
        __syncthreads();
        const float* Wp = expW + (size_t)e*16384 + (size_t)(gk*64)*128 + o;
        float acc[16];
#pragma unroll
        for (int r = 0; r < 16; r++) acc[r] = 0.f;
#pragma unroll 4
        for (int i4 = 0; i4 < 16; i4++){
            float w0 = Wp[(i4*4+0)*128];
            float w1 = Wp[(i4*4+1)*128];
            float w2 = Wp[(i4*4+2)*128];
            float w3 = Wp[(i4*4+3)*128];
#pragma unroll
            for (int r = 0; r < 16; r++){
                float4 h4 = ((const float4*)(hs + r*128 + gk*64))[i4];
                acc[r] += h4.x*w0 + h4.y*w1 + h4.z*w2 + h4.w*w3;
            }
        }
        if (gk){
#pragma unroll
            for (int r = 0; r < 16; r++) red[r*128 + o] = acc[r];
        }
        __syncthreads();
        if (!gk){
            for (int r = 0; r < m; r++){
                int pk = toks[r];
                g_y[(size_t)(pk >> 1)*256 + (pk & 1)*128 + o] = acc[r] + red[r*128 + o];
            }
        }
        __syncthreads();
    }
}

// ---------------- K5: wavg -> swiglu(m1,m2) -> residual + consensus (8-token tile) ----------------
__global__ void k_moe_b(const float* __restrict__ m1W, const float* __restrict__ m1b,
                        const float* __restrict__ m2W, const float* __restrict__ m2b,
                        float* __restrict__ out, float* __restrict__ cons){
    __shared__ __align__(16) float aT [1024];
    __shared__ __align__(16) float red[1024];
    __shared__ float ews[16];
    int tid = threadIdx.x;
    int c = tid & 127, g = tid >> 7;
    int w = tid >> 5,  l = tid & 31;
    int t0 = blockIdx.x*8;

    if (tid < 16) ews[tid] = g_ew[t0*2 + tid];
#pragma unroll
    for (int j = 0; j < 4; j++){
        int q = tid + 256*j;
        int r = q & 7, o = q >> 3;
        size_t t = t0 + r;
        aT[q] = g_ew[2*t]*g_y[t*256 + o] + g_ew[2*t+1]*g_y[t*256 + 128 + o];
    }
    __syncthreads();

    float ag[8], au[8];
    mm8h_dual(aT, m1W, m2W, c, g, ag, au);
    if (g){
#pragma unroll
        for (int r = 0; r < 8; r++) red[c*8+r] = ag[r];
    }
    __syncthreads();
    if (!g){
#pragma unroll
        for (int r = 0; r < 8; r++) ag[r] += red[c*8+r];
    }
    __syncthreads();
    if (g){
#pragma unroll
        for (int r = 0; r < 8; r++) red[c*8+r] = au[r];
    }
    __syncthreads();
    if (!g){
        float b1 = m1b[c], b2 = m2b[c];
#pragma unroll
        for (int r = 0; r < 8; r++){
            size_t t = t0 + r;
            float gg = ag[r] + b1;
            float uu = au[r] + red[c*8+r] + b2;
            float ws = silu(gg)*uu;
            out[t*DD + c] = g_x2[t*DD + c] + ws;
            float w1 = ews[2*r], w2 = ews[2*r+1];
            float y1 = g_y[t*256 + c];
            float y2 = g_y[t*256 + 128 + c];
            float d1 = y1 - ws, d2 = y2 - ws;
            red[c*8+r] = w1*d1*d1 + w2*d2*d2;   // reuse red as wvar tile
        }
    }
    __syncthreads();

    // consensus: warp w -> token w
    {
        float s = 0.f;
#pragma unroll
        for (int j = 0; j < 4; j++) s += red[(l+32*j)*8 + w];
        s = warp_sum(s);
        if (l == 0) cons[t0 + w] = expf(-s*(1.f/128.f));
    }
}

// ---------------- launch ----------------
extern "C" void kernel_launch(void* const* d_in, const int* in_sizes, int n_in,
                              void* d_out, int out_size){
    const float* x    = (const float*)d_in[0];
    const float* g1   = (const float*)d_in[1];
    const float* qW   = (const float*)d_in[2];
    const float* qb   = (const float*)d_in[3];
    const float* kdW  = (const float*)d_in[4];
    const float* kdb  = (const float*)d_in[5];
    const float* kuW  = (const float*)d_in[6];
    const float* kub  = (const float*)d_in[7];
    const float* oW   = (const float*)d_in[8];
    const float* ob   = (const float*)d_in[9];
    const float* rot  = (const float*)d_in[10];
    const float* tqs  = (const float*)d_in[11];
    const float* s1W  = (const float*)d_in[12];
    const float* s1b  = (const float*)d_in[13];
    const float* s2W  = (const float*)d_in[14];
    const float* s2b  = (const float*)d_in[15];
    const float* g2   = (const float*)d_in[16];
    const float* gateW= (const float*)d_in[17];
    const float* gateb= (const float*)d_in[18];
    const float* expW = (const float*)d_in[19];
    const float* m1W  = (const float*)d_in[20];
    const float* m1b  = (const float*)d_in[21];
    const float* m2W  = (const float*)d_in[22];
    const float* m2b  = (const float*)d_in[23];

    float* out  = (float*)d_out;
    float* cons = out + (size_t)NT*DD;

    k_pre  <<<NT/8, 256>>>(x, g1, qW, qb, kdW, kdb, kuW, kub);
    k_ctx  <<<BB*HH*4, 256>>>();
    k_fused<<<NT/8, 256>>>(oW, ob, rot, tqs, s1W, s1b, s2W, s2b, x, g2, gateW, gateb);
    k_moe  <<<512, 256>>>(expW);
    k_moe_b<<<NT/8, 256>>>(m1W, m1b, m2W, m2b, out, cons);
}